// round 8
// baseline (speedup 1.0000x reference)
#include <cuda_runtime.h>
#include <cuda_bf16.h>
#include <cstdint>
#include <math.h>

// Problem constants
#define NSEG 500000
#define HID 128
#define NBLK 4
#define THREADS 256
#define NSM 148              // persistent grid size
#define PITCHB 144           // bytes per s8 tile row (16B pad, ldmatrix-conflict-free)
#define RMS_EPS 1.1920929e-07f

#define TILE_B  (128 * PITCHB)               // bytes per 128x128 s8 tile (18432)
#define OFF_W   0                            // 4 weight tiles (73728)
#define OFF_G   (4 * TILE_B)                 // 1 g tile (half-private rows)
#define OFF_RS  (5 * TILE_B)                 // rsum[128][8] floats (4096 B)
#define OFF_CST (OFF_RS + 4096)              // consts: 2176 floats (8704 B)
#define OFF_XS  (OFF_CST + 8704)             // xs double buffer 2*384 floats
#define SMEM_TOTAL (OFF_XS + 3072)

// Scratch (device globals — no allocation allowed)
__device__ float   g_ssum[NSEG];
__device__ uint8_t g_ws8[NBLK * HID * HID];  // per-column-quantized weights
__device__ float   g_cscale[NBLK * HID];     // per-column dequant scales

__device__ __forceinline__ uint32_t smem_u32(const void* p) {
    uint32_t a;
    asm("{ .reg .u64 t; cvta.to.shared.u64 t, %1; cvt.u32.u64 %0, t; }"
        : "=r"(a) : "l"(p));
    return a;
}
__device__ __forceinline__ uint32_t prmt(uint32_t a, uint32_t b, uint32_t sel) {
    uint32_t r;
    asm("prmt.b32 %0, %1, %2, %3;" : "=r"(r) : "r"(a), "r"(b), "r"(sel));
    return r;
}

#define CP_ASYNC16(dst, src) \
    asm volatile("cp.async.cg.shared.global [%0], [%1], 16;" \
                 :: "r"(dst), "l"(src) : "memory")
#define CP_COMMIT asm volatile("cp.async.commit_group;" ::: "memory")
#define CP_WAIT0  asm volatile("cp.async.wait_group 0;" ::: "memory")

// Half-CTA named barrier (128 threads each; ids 1 and 2)
#define BAR_HALF(id) asm volatile("bar.sync %0, 128;" :: "r"(id) : "memory")

#define LDMATRIX_X4(r0, r1, r2, r3, addr) \
    asm volatile("ldmatrix.sync.aligned.m8n8.x4.shared.b16 {%0,%1,%2,%3}, [%4];" \
                 : "=r"(r0), "=r"(r1), "=r"(r2), "=r"(r3) : "r"(addr))

// D(16x8,s32) += A(16x32 s8, row) * B(32x8 s8, col)
#define MMA_S8(d, a, b0, b1) \
    asm volatile("mma.sync.aligned.m16n8k32.row.col.s32.s8.s8.s32 " \
        "{%0,%1,%2,%3}, {%4,%5,%6,%7}, {%8,%9}, {%0,%1,%2,%3};" \
        : "+r"((d)[0]), "+r"((d)[1]), "+r"((d)[2]), "+r"((d)[3]) \
        : "r"((a)[0]), "r"((a)[1]), "r"((a)[2]), "r"((a)[3]), \
          "r"(b0), "r"(b1))

// ---------------------------------------------------------------------------
// Per-column weight quantization: one warp per output column (512 warps).
// ---------------------------------------------------------------------------
__global__ void w_quant_kernel(const float* __restrict__ W_res) {
    int gw   = (blockIdx.x * blockDim.x + threadIdx.x) >> 5;  // 0..511
    int lane = threadIdx.x & 31;
    if (gw >= NBLK * HID) return;
    const float4 v = *(const float4*)(W_res + gw * HID + lane * 4);
    float m = fmaxf(fmaxf(fabsf(v.x), fabsf(v.y)), fmaxf(fabsf(v.z), fabsf(v.w)));
    #pragma unroll
    for (int s = 16; s; s >>= 1) m = fmaxf(m, __shfl_xor_sync(0xffffffffu, m, s));
    m = fmaxf(m, 1e-20f);
    float inv = __fdividef(127.0f, m);
    int q0 = __float2int_rn(v.x * inv), q1 = __float2int_rn(v.y * inv);
    int q2 = __float2int_rn(v.z * inv), q3 = __float2int_rn(v.w * inv);
    uint32_t t0 = prmt((uint32_t)q0, (uint32_t)q1, 0x0040);
    uint32_t t1 = prmt((uint32_t)q2, (uint32_t)q3, 0x0040);
    ((uint32_t*)g_ws8)[gw * 32 + lane] = prmt(t0, t1, 0x5410);
    if (lane == 0) g_cscale[gw] = m * (1.0f / 127.0f);
}

__global__ void seg_init_kernel() {
    int i = blockIdx.x * blockDim.x + threadIdx.x;
    if (i < NSEG) g_ssum[i] = 0.0f;
}

// ---------------------------------------------------------------------------
// Persistent fused MLP on int8 mma.m16n8k32. h in fp32 fragment registers.
// Per-row dynamic activation quantization; per-column weight scales.
// ---------------------------------------------------------------------------
__global__ void __launch_bounds__(THREADS, 1)
mlp_mma_kernel(const float* __restrict__ x,
               const int*   __restrict__ ids,
               const float* __restrict__ W_in,
               const float* __restrict__ b_in,
               const float* __restrict__ rms_w,
               const float* __restrict__ b_res,
               const float* __restrict__ W_out,
               const float* __restrict__ b_out,
               float* __restrict__ out,
               int n, int ntiles)
{
    extern __shared__ char smem[];
    float* rsum   = (float*)(smem + OFF_RS);      // [128][8]: 0-3 sumsq, 4-7 amax
    float* win_s  = (float*)(smem + OFF_CST);     // 384
    float* bin_s  = win_s + 384;                  // 128
    float* rws_s  = bin_s + 128;                  // 512
    float* bbs_s  = rws_s + 512;                  // 512
    float* wout_s = bbs_s + 512;                  // 128
    float* css_s  = wout_s + 128;                 // 512
    float* xs_all = (float*)(smem + OFF_XS);      // [2][384]

    const int t      = threadIdx.x;
    const int warp   = t >> 5;
    const int lane   = t & 31;
    const int gid    = lane >> 2;
    const int tig    = lane & 3;
    const int warp_m = warp >> 2;       // 0..1 -> half id
    const int warp_n = warp & 3;
    const int m0     = warp_m * 64;
    const int n0w    = warp_n * 32;
    const int tid128 = t & 127;
    const int barid  = 1 + warp_m;

    const uint32_t wbase = smem_u32(smem + OFF_W);
    const uint32_t gbase = smem_u32(smem + OFF_G);
    const uint32_t xbase = smem_u32(xs_all);

    // ---- Stage consts once
    for (int i = t; i < 384; i += THREADS) win_s[i] = W_in[i];
    for (int i = t; i < 128; i += THREADS) {
        bin_s[i]  = b_in[i];
        wout_s[i] = W_out[i];
    }
    for (int i = t; i < 512; i += THREADS) {
        rws_s[i] = rms_w[i];
        bbs_s[i] = b_res[i];
        css_s[i] = g_cscale[i];
    }
    // ---- Stage ALL 4 weight tiles once (s8, 16B chunks)
    #pragma unroll
    for (int it = 0; it < 16; it++) {
        int i   = t + it * THREADS;     // 0..4095 (16B chunks)
        int nrg = i >> 3;               // row 0..511
        int kc  = i & 7;
        CP_ASYNC16(wbase + (uint32_t)(nrg * PITCHB + kc * 16),
                   g_ws8 + nrg * HID + kc * 16);
    }
    CP_COMMIT;
    CP_WAIT0;
    __syncthreads();   // consts + W visible CTA-wide

    const float bout = b_out[0];

    // ldmatrix lane addresses (bytes; s8-k32 frag == b16-k16 frag byte layout)
    const uint32_t a_off = (uint32_t)(m0 + (lane & 15)) * PITCHB
                           + (uint32_t)(lane >> 4) * 16;
    const int b_row = n0w + ((lane >> 4) * 8) + (lane & 7);
    const uint32_t b_off = (uint32_t)b_row * PITCHB
                           + (uint32_t)(((lane >> 3) & 1) * 16);

    bool pf_next = false;
    int  buf     = 0;

    for (int tile = blockIdx.x; tile < ntiles; tile += NSM, buf ^= 1) {
        const int row0 = tile * 128;
        float* xsb = xs_all + buf * 384;

        if (pf_next) {
            CP_WAIT0;
        } else {
            for (int i = tid128; i < 192; i += 128) {
                int idx = m0 * 3 + i;
                long long gi = (long long)row0 * 3 + idx;
                xsb[idx] = (gi < 3LL * n) ? x[gi] : 0.0f;
            }
        }
        BAR_HALF(barid);

        // ---- In-projection into fragment registers
        float hv[64];
        {
            float wc[8][3], bc[8];
            #pragma unroll
            for (int nt = 0; nt < 4; nt++) {
                int c0 = n0w + nt * 8 + 2 * tig;
                #pragma unroll
                for (int k = 0; k < 3; k++) {
                    wc[nt * 2 + 0][k] = win_s[c0 * 3 + k];
                    wc[nt * 2 + 1][k] = win_s[(c0 + 1) * 3 + k];
                }
                bc[nt * 2 + 0] = bin_s[c0];
                bc[nt * 2 + 1] = bin_s[c0 + 1];
            }
            #pragma unroll
            for (int mt = 0; mt < 4; mt++) {
                int r0 = m0 + mt * 16 + gid;
                float a0 = xsb[r0 * 3], a1 = xsb[r0 * 3 + 1], a2 = xsb[r0 * 3 + 2];
                float d0 = xsb[(r0 + 8) * 3], d1 = xsb[(r0 + 8) * 3 + 1], d2 = xsb[(r0 + 8) * 3 + 2];
                #pragma unroll
                for (int nt = 0; nt < 4; nt++) {
                    #pragma unroll
                    for (int p = 0; p < 2; p++) {
                        float* w = wc[nt * 2 + p];
                        hv[(mt * 4 + nt) * 4 + p] =
                            fmaf(a2, w[2], fmaf(a1, w[1], fmaf(a0, w[0], bc[nt * 2 + p])));
                        hv[(mt * 4 + nt) * 4 + 2 + p] =
                            fmaf(d2, w[2], fmaf(d1, w[1], fmaf(d0, w[0], bc[nt * 2 + p])));
                    }
                }
            }
        }

        // ---- Residual blocks
        for (int b = 0; b < NBLK; b++) {
            // qv = h * rms_w; reduce sumsq(h) and amax(|qv|) per row
            float qv[64];
            float2 rwv[4];
            #pragma unroll
            for (int nt = 0; nt < 4; nt++)
                rwv[nt] = *(const float2*)&rws_s[b * HID + n0w + nt * 8 + 2 * tig];
            #pragma unroll
            for (int mt = 0; mt < 4; mt++) {
                float p0 = 0.f, p1 = 0.f, a0m = 0.f, a1m = 0.f;
                #pragma unroll
                for (int nt = 0; nt < 4; nt++) {
                    int ix = (mt * 4 + nt) * 4;
                    float e0 = hv[ix], e1 = hv[ix + 1], e2 = hv[ix + 2], e3 = hv[ix + 3];
                    float q0 = e0 * rwv[nt].x, q1 = e1 * rwv[nt].y;
                    float q2 = e2 * rwv[nt].x, q3 = e3 * rwv[nt].y;
                    qv[ix] = q0; qv[ix + 1] = q1; qv[ix + 2] = q2; qv[ix + 3] = q3;
                    p0 = fmaf(e0, e0, fmaf(e1, e1, p0));
                    p1 = fmaf(e2, e2, fmaf(e3, e3, p1));
                    a0m = fmaxf(a0m, fmaxf(fabsf(q0), fabsf(q1)));
                    a1m = fmaxf(a1m, fmaxf(fabsf(q2), fabsf(q3)));
                }
                p0 += __shfl_xor_sync(0xffffffffu, p0, 1);
                p0 += __shfl_xor_sync(0xffffffffu, p0, 2);
                p1 += __shfl_xor_sync(0xffffffffu, p1, 1);
                p1 += __shfl_xor_sync(0xffffffffu, p1, 2);
                a0m = fmaxf(a0m, __shfl_xor_sync(0xffffffffu, a0m, 1));
                a0m = fmaxf(a0m, __shfl_xor_sync(0xffffffffu, a0m, 2));
                a1m = fmaxf(a1m, __shfl_xor_sync(0xffffffffu, a1m, 1));
                a1m = fmaxf(a1m, __shfl_xor_sync(0xffffffffu, a1m, 2));
                if (tig == 0) {
                    int r0 = m0 + mt * 16 + gid;
                    rsum[r0 * 8 + warp_n]           = p0;
                    rsum[r0 * 8 + 4 + warp_n]       = a0m;
                    rsum[(r0 + 8) * 8 + warp_n]     = p1;
                    rsum[(r0 + 8) * 8 + 4 + warp_n] = a1m;
                }
            }
            BAR_HALF(barid);   // [A] rowsum/amax visible; half's g rows free

            // row scales + quantize g -> s8 tile (u16 stores of col pairs)
            float rs[4][2];
            #pragma unroll
            for (int mt = 0; mt < 4; mt++) {
                int r0 = m0 + mt * 16 + gid;
                float4 s0 = *(const float4*)&rsum[r0 * 8];
                float4 m0v = *(const float4*)&rsum[r0 * 8 + 4];
                float4 s1 = *(const float4*)&rsum[(r0 + 8) * 8];
                float4 m1v = *(const float4*)&rsum[(r0 + 8) * 8 + 4];
                float sc0 = rsqrtf((s0.x + s0.y + s0.z + s0.w) * (1.0f / HID) + RMS_EPS);
                float sc1 = rsqrtf((s1.x + s1.y + s1.z + s1.w) * (1.0f / HID) + RMS_EPS);
                float am0 = fmaxf(fmaxf(m0v.x, m0v.y), fmaxf(m0v.z, m0v.w));
                float am1 = fmaxf(fmaxf(m1v.x, m1v.y), fmaxf(m1v.z, m1v.w));
                am0 = fmaxf(am0, 1e-20f);
                am1 = fmaxf(am1, 1e-20f);
                float inv0 = __fdividef(127.0f, am0);
                float inv1 = __fdividef(127.0f, am1);
                rs[mt][0] = am0 * sc0 * (1.0f / 127.0f);
                rs[mt][1] = am1 * sc1 * (1.0f / 127.0f);
                #pragma unroll
                for (int nt = 0; nt < 4; nt++) {
                    int ix = (mt * 4 + nt) * 4;
                    int c0 = n0w + nt * 8 + 2 * tig;
                    int i0 = __float2int_rn(qv[ix] * inv0);
                    int i1 = __float2int_rn(qv[ix + 1] * inv0);
                    int i2 = __float2int_rn(qv[ix + 2] * inv1);
                    int i3 = __float2int_rn(qv[ix + 3] * inv1);
                    uint32_t u0 = prmt((uint32_t)i0, (uint32_t)i1, 0x0040);
                    uint32_t u1 = prmt((uint32_t)i2, (uint32_t)i3, 0x0040);
                    asm volatile("st.shared.u16 [%0], %1;"
                        :: "r"(gbase + (uint32_t)(r0 * PITCHB + c0)), "r"(u0) : "memory");
                    asm volatile("st.shared.u16 [%0], %1;"
                        :: "r"(gbase + (uint32_t)((r0 + 8) * PITCHB + c0)), "r"(u1) : "memory");
                }
            }
            BAR_HALF(barid);   // [B] half's g rows ready

            // Prefetch next tile's x during block 0
            if (b == 0) {
                int nxt = tile + NSM;
                if (nxt < ntiles && (long long)(nxt + 1) * 128 <= (long long)n) {
                    if (tid128 < 48) {
                        uint32_t dst = xbase + (uint32_t)((buf ^ 1) * 1536 + m0 * 12
                                                          + tid128 * 16);
                        const char* src = (const char*)x + (long long)nxt * 1536
                                          + m0 * 12 + tid128 * 16;
                        CP_ASYNC16(dst, src);
                    }
                    CP_COMMIT;
                    pf_next = true;
                } else {
                    pf_next = false;
                }
            }

            // GEMM: int8 mma, warp tile 64r x 32c, k-step 32 bytes
            int acc[4][4][4];
            #pragma unroll
            for (int mt = 0; mt < 4; mt++)
                #pragma unroll
                for (int nt = 0; nt < 4; nt++) {
                    acc[mt][nt][0] = 0; acc[mt][nt][1] = 0;
                    acc[mt][nt][2] = 0; acc[mt][nt][3] = 0;
                }
            const uint32_t a_base = gbase + a_off;
            const uint32_t b_base = wbase + (uint32_t)b * TILE_B + b_off;
            #pragma unroll
            for (int ks = 0; ks < 4; ks++) {
                const uint32_t koff = (uint32_t)ks * 32;
                uint32_t a[4][4];
                #pragma unroll
                for (int mt = 0; mt < 4; mt++)
                    LDMATRIX_X4(a[mt][0], a[mt][1], a[mt][2], a[mt][3],
                                a_base + (uint32_t)mt * (16 * PITCHB) + koff);
                uint32_t bf[4][2];
                #pragma unroll
                for (int np = 0; np < 2; np++)
                    LDMATRIX_X4(bf[np*2][0], bf[np*2][1], bf[np*2+1][0], bf[np*2+1][1],
                                b_base + (uint32_t)np * (16 * PITCHB) + koff);
                #pragma unroll
                for (int nt = 0; nt < 4; nt++)
                    #pragma unroll
                    for (int mt = 0; mt < 4; mt++)
                        MMA_S8(acc[mt][nt], a[mt], bf[nt][0], bf[nt][1]);
            }

            // dequant + residual: h += relu(f32(acc)*rs*cs + bias)
            #pragma unroll
            for (int nt = 0; nt < 4; nt++) {
                int c0 = n0w + nt * 8 + 2 * tig;
                float2 cs   = *(const float2*)&css_s[b * HID + c0];
                float2 bias = *(const float2*)&bbs_s[b * HID + c0];
                #pragma unroll
                for (int mt = 0; mt < 4; mt++) {
                    int ix = (mt * 4 + nt) * 4;
                    float p00 = rs[mt][0] * cs.x, p01 = rs[mt][0] * cs.y;
                    float p10 = rs[mt][1] * cs.x, p11 = rs[mt][1] * cs.y;
                    hv[ix]     += fmaxf(fmaf(__int2float_rn(acc[mt][nt][0]), p00, bias.x), 0.0f);
                    hv[ix + 1] += fmaxf(fmaf(__int2float_rn(acc[mt][nt][1]), p01, bias.y), 0.0f);
                    hv[ix + 2] += fmaxf(fmaf(__int2float_rn(acc[mt][nt][2]), p10, bias.x), 0.0f);
                    hv[ix + 3] += fmaxf(fmaf(__int2float_rn(acc[mt][nt][3]), p11, bias.y), 0.0f);
                }
            }
        }

        // ---- Output projection (per-half reduction via rsum)
        #pragma unroll
        for (int mt = 0; mt < 4; mt++) {
            float o0 = 0.f, o1 = 0.f;
            #pragma unroll
            for (int nt = 0; nt < 4; nt++) {
                int c0 = n0w + nt * 8 + 2 * tig;
                float2 w = *(const float2*)&wout_s[c0];
                int ix = (mt * 4 + nt) * 4;
                o0 = fmaf(hv[ix], w.x, fmaf(hv[ix + 1], w.y, o0));
                o1 = fmaf(hv[ix + 2], w.x, fmaf(hv[ix + 3], w.y, o1));
            }
            o0 += __shfl_xor_sync(0xffffffffu, o0, 1);
            o0 += __shfl_xor_sync(0xffffffffu, o0, 2);
            o1 += __shfl_xor_sync(0xffffffffu, o1, 1);
            o1 += __shfl_xor_sync(0xffffffffu, o1, 2);
            if (tig == 0) {
                int r0 = m0 + mt * 16 + gid;
                rsum[r0 * 8 + warp_n]       = o0;
                rsum[(r0 + 8) * 8 + warp_n] = o1;
            }
        }
        BAR_HALF(barid);
        if (tid128 < 64) {
            int r = m0 + tid128;
            long long gr = (long long)row0 + r;
            if (gr < n) {
                float4 s = *(const float4*)&rsum[r * 8];
                float lg = s.x + s.y + s.z + s.w + bout;
                float e = expf(lg);
                out[gr] = e;
                atomicAdd(&g_ssum[ids[gr]], e);
            }
        }
    }
}

// ---------------------------------------------------------------------------
// Normalize (vectorized): out[i] /= ssum[ids[i]]
// ---------------------------------------------------------------------------
__global__ void seg_norm_kernel(const int* __restrict__ ids,
                                float* __restrict__ out, int n)
{
    int i4 = blockIdx.x * blockDim.x + threadIdx.x;
    int i = i4 * 4;
    if (i + 3 < n) {
        int4   s = *(const int4*)&ids[i];
        float4 v = *(float4*)&out[i];
        v.x /= g_ssum[s.x];
        v.y /= g_ssum[s.y];
        v.z /= g_ssum[s.z];
        v.w /= g_ssum[s.w];
        *(float4*)&out[i] = v;
    } else {
        for (int j = i; j < n; j++) out[j] /= g_ssum[ids[j]];
    }
}

// ---------------------------------------------------------------------------
extern "C" void kernel_launch(void* const* d_in, const int* in_sizes, int n_in,
                              void* d_out, int out_size)
{
    const float* x     = (const float*)d_in[0];
    const int*   ids   = (const int*)  d_in[1];
    const float* W_in  = (const float*)d_in[2];
    const float* b_in  = (const float*)d_in[3];
    const float* rms_w = (const float*)d_in[4];
    const float* W_res = (const float*)d_in[5];
    const float* b_res = (const float*)d_in[6];
    const float* W_out = (const float*)d_in[7];
    const float* b_out = (const float*)d_in[8];
    float* out = (float*)d_out;
    const int n = in_sizes[1];
    const int ntiles = (n + 127) / 128;

    cudaFuncSetAttribute(mlp_mma_kernel,
                         cudaFuncAttributeMaxDynamicSharedMemorySize,
                         SMEM_TOTAL);

    w_quant_kernel<<<(NBLK * HID * 32 + 255) / 256, 256>>>(W_res);
    seg_init_kernel<<<(NSEG + 255) / 256, 256>>>();
    mlp_mma_kernel<<<NSM, THREADS, SMEM_TOTAL>>>(
        x, ids, W_in, b_in, rms_w, b_res, W_out, b_out, out, n, ntiles);
    seg_norm_kernel<<<((n + 3) / 4 + 255) / 256, 256>>>(ids, out, n);
}

// round 9
// speedup vs baseline: 2.5238x; 2.5238x over previous
#include <cuda_runtime.h>
#include <cuda_bf16.h>
#include <cstdint>
#include <math.h>

// Problem constants
#define NSEG 500000
#define HID 128
#define NBLK 4
#define THREADS 256
#define NSM 148              // persistent grid size
#define PITCHH 136           // halfs per bf16 tile row (ldmatrix-conflict-free pad)
#define RMS_EPS 1.1920929e-07f

#define TILE_HB (128 * PITCHH * 2)          // bytes per 128x128 bf16 tile (34816)
#define OFF_W   0                            // 4 weight tiles
#define OFF_G   (4 * TILE_HB)                // 1 g tile (half-private rows)
#define OFF_RS  (5 * TILE_HB)                // rowsum[128][4] floats (2048 B)
#define OFF_CST (OFF_RS + 2048)              // consts: 1664 floats (6656 B)
#define OFF_XS  (OFF_CST + 6656)             // xs double buffer 2*384 floats (3072 B)
#define SMEM_TOTAL (OFF_XS + 3072)

// Scratch (device globals — no allocation allowed)
__device__ float         g_ssum[NSEG];
__device__ __nv_bfloat16 g_wbf[NBLK * HID * HID];

__device__ __forceinline__ uint32_t smem_u32(const void* p) {
    uint32_t a;
    asm("{ .reg .u64 t; cvta.to.shared.u64 t, %1; cvt.u32.u64 %0, t; }"
        : "=r"(a) : "l"(p));
    return a;
}
__device__ __forceinline__ uint32_t bf16x2(float lo, float hi) {
    uint32_t r;
    asm("cvt.rn.bf16x2.f32 %0, %1, %2;" : "=r"(r) : "f"(hi), "f"(lo));
    return r;
}

#define CP_ASYNC16(dst, src) \
    asm volatile("cp.async.cg.shared.global [%0], [%1], 16;" \
                 :: "r"(dst), "l"(src) : "memory")
#define CP_COMMIT asm volatile("cp.async.commit_group;" ::: "memory")
#define CP_WAIT0  asm volatile("cp.async.wait_group 0;" ::: "memory")

// Half-CTA named barrier (128 threads each; ids 1 and 2)
#define BAR_HALF(id) asm volatile("bar.sync %0, 128;" :: "r"(id) : "memory")

#define LDMATRIX_X4(r0, r1, r2, r3, addr) \
    asm volatile("ldmatrix.sync.aligned.m8n8.x4.shared.b16 {%0,%1,%2,%3}, [%4];" \
                 : "=r"(r0), "=r"(r1), "=r"(r2), "=r"(r3) : "r"(addr))

#define MMA_BF16(d, a0, a1, a2, a3, b0, b1) \
    asm volatile("mma.sync.aligned.m16n8k16.row.col.f32.bf16.bf16.f32 " \
        "{%0,%1,%2,%3}, {%4,%5,%6,%7}, {%8,%9}, {%0,%1,%2,%3};" \
        : "+f"((d)[0]), "+f"((d)[1]), "+f"((d)[2]), "+f"((d)[3]) \
        : "r"(a0), "r"(a1), "r"(a2), "r"(a3), "r"(b0), "r"(b1))

// ---------------------------------------------------------------------------
// Prep: convert W to bf16 + zero segment sums (one kernel)
// ---------------------------------------------------------------------------
__global__ void prep_kernel(const float* __restrict__ W_res) {
    int i = blockIdx.x * blockDim.x + threadIdx.x;
    if (i < NBLK * HID * HID) g_wbf[i] = __float2bfloat16_rn(W_res[i]);
    if (i < NSEG) g_ssum[i] = 0.0f;
}

// ---------------------------------------------------------------------------
// Persistent fused MLP (bf16 mma). h in fragment registers end-to-end.
// Two free-running 64-row halves. Own-A-fragment shortcut: k-chunks
// 2*warp_n, 2*warp_n+1 use register A operands, issued pre-barrier.
// ---------------------------------------------------------------------------
__global__ void __launch_bounds__(THREADS, 1)
mlp_mma_kernel(const float* __restrict__ x,
               const int*   __restrict__ ids,
               const float* __restrict__ W_in,
               const float* __restrict__ b_in,
               const float* __restrict__ rms_w,
               const float* __restrict__ b_res,
               const float* __restrict__ W_out,
               const float* __restrict__ b_out,
               float* __restrict__ out,
               int n, int ntiles)
{
    extern __shared__ char smem[];
    float* rsum   = (float*)(smem + OFF_RS);      // [128][4]
    float* win_s  = (float*)(smem + OFF_CST);     // 384
    float* bin_s  = win_s + 384;                  // 128
    float* rws_s  = bin_s + 128;                  // 512
    float* bbs_s  = rws_s + 512;                  // 512
    float* wout_s = bbs_s + 512;                  // 128
    float* xs_all = (float*)(smem + OFF_XS);      // [2][384]

    const int t      = threadIdx.x;
    const int warp   = t >> 5;
    const int lane   = t & 31;
    const int gid    = lane >> 2;
    const int tig    = lane & 3;
    const int warp_m = warp >> 2;       // 0..1 -> half id
    const int warp_n = warp & 3;
    const int m0     = warp_m * 64;
    const int n0w    = warp_n * 32;
    const int tid128 = t & 127;
    const int barid  = 1 + warp_m;
    const int wn2    = warp_n * 2;      // own k-chunk base

    const uint32_t wbase = smem_u32(smem + OFF_W);
    const uint32_t gbase = smem_u32(smem + OFF_G);
    const uint32_t xbase = smem_u32(xs_all);

    // ---- Stage consts once
    for (int i = t; i < 384; i += THREADS) win_s[i] = W_in[i];
    for (int i = t; i < 128; i += THREADS) {
        bin_s[i]  = b_in[i];
        wout_s[i] = W_out[i];
    }
    for (int i = t; i < 512; i += THREADS) {
        rws_s[i] = rms_w[i];
        bbs_s[i] = b_res[i];
    }
    // ---- Stage ALL 4 weight tiles once (bf16, 16B chunks)
    #pragma unroll
    for (int it = 0; it < 32; it++) {
        int i   = t + it * THREADS;     // 0..8191
        int nrg = i >> 4;               // blk*128 + row
        int kc  = i & 15;
        CP_ASYNC16(wbase + (uint32_t)(nrg * PITCHH + kc * 8) * 2,
                   g_wbf + nrg * HID + kc * 8);
    }
    CP_COMMIT;
    CP_WAIT0;
    __syncthreads();   // consts + W visible CTA-wide

    const float bout = b_out[0];

    // ldmatrix lane addresses (fixed)
    const uint32_t a_off = ((uint32_t)(m0 + (lane & 15)) * PITCHH
                           + (uint32_t)(lane >> 4) * 8) * 2;
    const int b_row = n0w + ((lane >> 4) * 8) + (lane & 7);
    const uint32_t b_off = ((uint32_t)b_row * PITCHH
                            + (uint32_t)(((lane >> 3) & 1) * 8)) * 2;

    bool pf_next = false;
    int  buf     = 0;

    for (int tile = blockIdx.x; tile < ntiles; tile += NSM, buf ^= 1) {
        const int row0 = tile * 128;
        float* xsb = xs_all + buf * 384;

        if (pf_next) {
            CP_WAIT0;
        } else {
            for (int i = tid128; i < 192; i += 128) {
                int idx = m0 * 3 + i;
                long long gi = (long long)row0 * 3 + idx;
                xsb[idx] = (gi < 3LL * n) ? x[gi] : 0.0f;
            }
        }
        BAR_HALF(barid);

        // ---- In-projection into fragment registers
        float hv[64];
        {
            float wc[8][3], bc[8];
            #pragma unroll
            for (int nt = 0; nt < 4; nt++) {
                int c0 = n0w + nt * 8 + 2 * tig;
                #pragma unroll
                for (int k = 0; k < 3; k++) {
                    wc[nt * 2 + 0][k] = win_s[c0 * 3 + k];
                    wc[nt * 2 + 1][k] = win_s[(c0 + 1) * 3 + k];
                }
                bc[nt * 2 + 0] = bin_s[c0];
                bc[nt * 2 + 1] = bin_s[c0 + 1];
            }
            #pragma unroll
            for (int mt = 0; mt < 4; mt++) {
                int r0 = m0 + mt * 16 + gid;
                float a0 = xsb[r0 * 3], a1 = xsb[r0 * 3 + 1], a2 = xsb[r0 * 3 + 2];
                float d0 = xsb[(r0 + 8) * 3], d1 = xsb[(r0 + 8) * 3 + 1], d2 = xsb[(r0 + 8) * 3 + 2];
                #pragma unroll
                for (int nt = 0; nt < 4; nt++) {
                    #pragma unroll
                    for (int p = 0; p < 2; p++) {
                        float* w = wc[nt * 2 + p];
                        hv[(mt * 4 + nt) * 4 + p] =
                            fmaf(a2, w[2], fmaf(a1, w[1], fmaf(a0, w[0], bc[nt * 2 + p])));
                        hv[(mt * 4 + nt) * 4 + 2 + p] =
                            fmaf(d2, w[2], fmaf(d1, w[1], fmaf(d0, w[0], bc[nt * 2 + p])));
                    }
                }
            }
        }

        // ---- Residual blocks
        for (int b = 0; b < NBLK; b++) {
            // rms partials into half-private rsum rows
            #pragma unroll
            for (int mt = 0; mt < 4; mt++) {
                float p0 = 0.f, p1 = 0.f;
                #pragma unroll
                for (int nt = 0; nt < 4; nt++) {
                    float e0 = hv[(mt*4+nt)*4+0], e1 = hv[(mt*4+nt)*4+1];
                    float e2 = hv[(mt*4+nt)*4+2], e3 = hv[(mt*4+nt)*4+3];
                    p0 = fmaf(e0, e0, fmaf(e1, e1, p0));
                    p1 = fmaf(e2, e2, fmaf(e3, e3, p1));
                }
                p0 += __shfl_xor_sync(0xffffffffu, p0, 1);
                p0 += __shfl_xor_sync(0xffffffffu, p0, 2);
                p1 += __shfl_xor_sync(0xffffffffu, p1, 1);
                p1 += __shfl_xor_sync(0xffffffffu, p1, 2);
                if (tig == 0) {
                    int r0 = m0 + mt * 16 + gid;
                    rsum[r0 * 4 + warp_n]       = p0;
                    rsum[(r0 + 8) * 4 + warp_n] = p1;
                }
            }
            BAR_HALF(barid);   // [A] rowsum visible; half's g rows free

            // scales + quantize to bf16; keep packed own-fragments in gq
            uint32_t gq[2][4][4];   // [own-k half][mt][a-reg]
            #pragma unroll
            for (int mt = 0; mt < 4; mt++) {
                int r0 = m0 + mt * 16 + gid;
                float4 s0 = *(const float4*)&rsum[r0 * 4];
                float4 s1 = *(const float4*)&rsum[(r0 + 8) * 4];
                float sc0 = rsqrtf((s0.x + s0.y + s0.z + s0.w) * (1.0f / HID) + RMS_EPS);
                float sc1 = rsqrtf((s1.x + s1.y + s1.z + s1.w) * (1.0f / HID) + RMS_EPS);
                #pragma unroll
                for (int nt = 0; nt < 4; nt++) {
                    int c0 = n0w + nt * 8 + 2 * tig;
                    float2 rw = *(const float2*)&rws_s[b * HID + c0];
                    uint32_t v0 = bf16x2(hv[(mt*4+nt)*4+0] * sc0 * rw.x,
                                         hv[(mt*4+nt)*4+1] * sc0 * rw.y);
                    uint32_t v1 = bf16x2(hv[(mt*4+nt)*4+2] * sc1 * rw.x,
                                         hv[(mt*4+nt)*4+3] * sc1 * rw.y);
                    gq[nt >> 1][mt][(nt & 1) * 2 + 0] = v0;
                    gq[nt >> 1][mt][(nt & 1) * 2 + 1] = v1;
                    asm volatile("st.shared.b32 [%0], %1;"
                        :: "r"(gbase + (uint32_t)(r0 * PITCHH + c0) * 2), "r"(v0) : "memory");
                    asm volatile("st.shared.b32 [%0], %1;"
                        :: "r"(gbase + (uint32_t)((r0 + 8) * PITCHH + c0) * 2), "r"(v1) : "memory");
                }
            }

            // Early GEMM: own k-chunks (A from registers, B resident) —
            // issued BEFORE the barrier to fill its shadow.
            float acc[4][4][4];
            #pragma unroll
            for (int mt = 0; mt < 4; mt++)
                #pragma unroll
                for (int nt = 0; nt < 4; nt++) {
                    acc[mt][nt][0] = 0.f; acc[mt][nt][1] = 0.f;
                    acc[mt][nt][2] = 0.f; acc[mt][nt][3] = 0.f;
                }
            const uint32_t a_base = gbase + a_off;
            const uint32_t b_base = wbase + (uint32_t)b * TILE_HB + b_off;
            #pragma unroll
            for (int hk = 0; hk < 2; hk++) {
                const uint32_t koff = (uint32_t)(wn2 + hk) * 32;
                uint32_t bf[4][2];
                #pragma unroll
                for (int np = 0; np < 2; np++)
                    LDMATRIX_X4(bf[np*2][0], bf[np*2][1], bf[np*2+1][0], bf[np*2+1][1],
                                b_base + (uint32_t)np * (16 * PITCHH * 2) + koff);
                #pragma unroll
                for (int nt = 0; nt < 4; nt++)
                    #pragma unroll
                    for (int mt = 0; mt < 4; mt++)
                        MMA_BF16(acc[mt][nt],
                                 gq[hk][mt][0], gq[hk][mt][1],
                                 gq[hk][mt][2], gq[hk][mt][3],
                                 bf[nt][0], bf[nt][1]);
            }
            BAR_HALF(barid);   // [B] half's g rows visible

            // Prefetch next tile's x during block 0
            if (b == 0) {
                int nxt = tile + NSM;
                if (nxt < ntiles && (long long)(nxt + 1) * 128 <= (long long)n) {
                    if (tid128 < 48) {
                        uint32_t dst = xbase + (uint32_t)((buf ^ 1) * 1536 + m0 * 12
                                                          + tid128 * 16);
                        const char* src = (const char*)x + (long long)nxt * 1536
                                          + m0 * 12 + tid128 * 16;
                        CP_ASYNC16(dst, src);
                    }
                    CP_COMMIT;
                    pf_next = true;
                } else {
                    pf_next = false;
                }
            }

            // Late GEMM: remaining 6 k-chunks (A via ldmatrix)
            #pragma unroll
            for (int j = 0; j < 6; j++) {
                const int ks = j + ((j >= wn2) ? 2 : 0);
                const uint32_t koff = (uint32_t)ks * 32;
                uint32_t a[4][4];
                #pragma unroll
                for (int mt = 0; mt < 4; mt++)
                    LDMATRIX_X4(a[mt][0], a[mt][1], a[mt][2], a[mt][3],
                                a_base + (uint32_t)mt * (16 * PITCHH * 2) + koff);
                uint32_t bf[4][2];
                #pragma unroll
                for (int np = 0; np < 2; np++)
                    LDMATRIX_X4(bf[np*2][0], bf[np*2][1], bf[np*2+1][0], bf[np*2+1][1],
                                b_base + (uint32_t)np * (16 * PITCHH * 2) + koff);
                #pragma unroll
                for (int nt = 0; nt < 4; nt++)
                    #pragma unroll
                    for (int mt = 0; mt < 4; mt++)
                        MMA_BF16(acc[mt][nt],
                                 a[mt][0], a[mt][1], a[mt][2], a[mt][3],
                                 bf[nt][0], bf[nt][1]);
            }

            // residual: h += relu(acc + bias)
            #pragma unroll
            for (int nt = 0; nt < 4; nt++) {
                int c0 = n0w + nt * 8 + 2 * tig;
                float2 bias = *(const float2*)&bbs_s[b * HID + c0];
                #pragma unroll
                for (int mt = 0; mt < 4; mt++) {
                    hv[(mt*4+nt)*4+0] += fmaxf(acc[mt][nt][0] + bias.x, 0.0f);
                    hv[(mt*4+nt)*4+1] += fmaxf(acc[mt][nt][1] + bias.y, 0.0f);
                    hv[(mt*4+nt)*4+2] += fmaxf(acc[mt][nt][2] + bias.x, 0.0f);
                    hv[(mt*4+nt)*4+3] += fmaxf(acc[mt][nt][3] + bias.y, 0.0f);
                }
            }
        }

        // ---- Output projection (per-half reduction)
        #pragma unroll
        for (int mt = 0; mt < 4; mt++) {
            float o0 = 0.f, o1 = 0.f;
            #pragma unroll
            for (int nt = 0; nt < 4; nt++) {
                int c0 = n0w + nt * 8 + 2 * tig;
                float2 w = *(const float2*)&wout_s[c0];
                o0 = fmaf(hv[(mt*4+nt)*4+0], w.x, fmaf(hv[(mt*4+nt)*4+1], w.y, o0));
                o1 = fmaf(hv[(mt*4+nt)*4+2], w.x, fmaf(hv[(mt*4+nt)*4+3], w.y, o1));
            }
            o0 += __shfl_xor_sync(0xffffffffu, o0, 1);
            o0 += __shfl_xor_sync(0xffffffffu, o0, 2);
            o1 += __shfl_xor_sync(0xffffffffu, o1, 1);
            o1 += __shfl_xor_sync(0xffffffffu, o1, 2);
            if (tig == 0) {
                int r0 = m0 + mt * 16 + gid;
                rsum[r0 * 4 + warp_n]       = o0;
                rsum[(r0 + 8) * 4 + warp_n] = o1;
            }
        }
        BAR_HALF(barid);
        if (tid128 < 64) {
            int r = m0 + tid128;
            long long gr = (long long)row0 + r;
            if (gr < n) {
                float4 s = *(const float4*)&rsum[r * 4];
                float lg = s.x + s.y + s.z + s.w + bout;
                float e = __expf(lg);
                out[gr] = e;
                atomicAdd(&g_ssum[ids[gr]], e);
            }
        }
    }
}

// ---------------------------------------------------------------------------
// Normalize (vectorized): out[i] /= ssum[ids[i]]
// ---------------------------------------------------------------------------
__global__ void seg_norm_kernel(const int* __restrict__ ids,
                                float* __restrict__ out, int n)
{
    int i4 = blockIdx.x * blockDim.x + threadIdx.x;
    int i = i4 * 4;
    if (i + 3 < n) {
        int4   s = *(const int4*)&ids[i];
        float4 v = *(float4*)&out[i];
        v.x /= g_ssum[s.x];
        v.y /= g_ssum[s.y];
        v.z /= g_ssum[s.z];
        v.w /= g_ssum[s.w];
        *(float4*)&out[i] = v;
    } else {
        for (int j = i; j < n; j++) out[j] /= g_ssum[ids[j]];
    }
}

// ---------------------------------------------------------------------------
extern "C" void kernel_launch(void* const* d_in, const int* in_sizes, int n_in,
                              void* d_out, int out_size)
{
    const float* x     = (const float*)d_in[0];
    const int*   ids   = (const int*)  d_in[1];
    const float* W_in  = (const float*)d_in[2];
    const float* b_in  = (const float*)d_in[3];
    const float* rms_w = (const float*)d_in[4];
    const float* W_res = (const float*)d_in[5];
    const float* b_res = (const float*)d_in[6];
    const float* W_out = (const float*)d_in[7];
    const float* b_out = (const float*)d_in[8];
    float* out = (float*)d_out;
    const int n = in_sizes[1];
    const int ntiles = (n + 127) / 128;

    cudaFuncSetAttribute(mlp_mma_kernel,
                         cudaFuncAttributeMaxDynamicSharedMemorySize,
                         SMEM_TOTAL);

    prep_kernel<<<(NSEG + 255) / 256, 256>>>(W_res);
    mlp_mma_kernel<<<NSM, THREADS, SMEM_TOTAL>>>(
        x, ids, W_in, b_in, rms_w, b_res, W_out, b_out, out, n, ntiles);
    seg_norm_kernel<<<((n + 3) / 4 + 255) / 256, 256>>>(ids, out, n);
}

// round 10
// speedup vs baseline: 2.5439x; 1.0080x over previous
#include <cuda_runtime.h>
#include <cuda_bf16.h>
#include <cstdint>
#include <math.h>

// Problem constants
#define NSEG 500000
#define HID 128
#define NBLK 4
#define THREADS 256
#define NSM 148              // persistent grid size
#define PITCHH 136           // halfs per bf16 tile row (ldmatrix-conflict-free pad)
#define RMS_EPS 1.1920929e-07f

#define TILE_HB (128 * PITCHH * 2)          // bytes per 128x128 bf16 tile (34816)
#define OFF_W   0                            // 4 weight tiles
#define OFF_G   (4 * TILE_HB)                // 1 g tile (half-private rows)
#define OFF_RS  (5 * TILE_HB)                // rowsum[128][4] floats (2048 B)
#define OFF_CST (OFF_RS + 2048)              // consts: 1664 floats (6656 B)
#define OFF_XS  (OFF_CST + 6656)             // xs double buffer 2*384 floats (3072 B)
#define SMEM_TOTAL (OFF_XS + 3072)

// Scratch (device globals — no allocation allowed)
__device__ float         g_ssum[NSEG];
__device__ __nv_bfloat16 g_wbf[NBLK * HID * HID];

__device__ __forceinline__ uint32_t smem_u32(const void* p) {
    uint32_t a;
    asm("{ .reg .u64 t; cvta.to.shared.u64 t, %1; cvt.u32.u64 %0, t; }"
        : "=r"(a) : "l"(p));
    return a;
}
__device__ __forceinline__ uint32_t bf16x2(float lo, float hi) {
    uint32_t r;
    asm("cvt.rn.bf16x2.f32 %0, %1, %2;" : "=r"(r) : "f"(hi), "f"(lo));
    return r;
}

#define CP_ASYNC16(dst, src) \
    asm volatile("cp.async.cg.shared.global [%0], [%1], 16;" \
                 :: "r"(dst), "l"(src) : "memory")
#define CP_COMMIT asm volatile("cp.async.commit_group;" ::: "memory")
#define CP_WAIT0  asm volatile("cp.async.wait_group 0;" ::: "memory")

// Half-CTA named barrier (128 threads each; ids 1 and 2)
#define BAR_HALF(id) asm volatile("bar.sync %0, 128;" :: "r"(id) : "memory")

#define LDMATRIX_X4(r0, r1, r2, r3, addr) \
    asm volatile("ldmatrix.sync.aligned.m8n8.x4.shared.b16 {%0,%1,%2,%3}, [%4];" \
                 : "=r"(r0), "=r"(r1), "=r"(r2), "=r"(r3) : "r"(addr))

#define MMA_BF16(d, a0, a1, a2, a3, b0, b1) \
    asm volatile("mma.sync.aligned.m16n8k16.row.col.f32.bf16.bf16.f32 " \
        "{%0,%1,%2,%3}, {%4,%5,%6,%7}, {%8,%9}, {%0,%1,%2,%3};" \
        : "+f"((d)[0]), "+f"((d)[1]), "+f"((d)[2]), "+f"((d)[3]) \
        : "r"(a0), "r"(a1), "r"(a2), "r"(a3), "r"(b0), "r"(b1))

// ---------------------------------------------------------------------------
// Prep (vectorized): zero segment sums (float4) + convert W to bf16 (float4
// -> 2x bf16x2 as uint2). One launch, small grid.
// ---------------------------------------------------------------------------
__global__ void prep_kernel(const float* __restrict__ W_res) {
    int i = blockIdx.x * blockDim.x + threadIdx.x;
    if (i < NSEG / 4)
        ((float4*)g_ssum)[i] = make_float4(0.f, 0.f, 0.f, 0.f);
    if (i < (NBLK * HID * HID) / 4) {
        float4 v = ((const float4*)W_res)[i];
        uint2 o;
        o.x = bf16x2(v.x, v.y);
        o.y = bf16x2(v.z, v.w);
        ((uint2*)g_wbf)[i] = o;
    }
}

// ---------------------------------------------------------------------------
// Persistent fused MLP (bf16 mma). h in fragment registers end-to-end.
// Two free-running 64-row halves. Own-A-fragment shortcut: k-chunks
// 2*warp_n, 2*warp_n+1 use register A operands, issued pre-barrier.
// ---------------------------------------------------------------------------
__global__ void __launch_bounds__(THREADS, 1)
mlp_mma_kernel(const float* __restrict__ x,
               const int*   __restrict__ ids,
               const float* __restrict__ W_in,
               const float* __restrict__ b_in,
               const float* __restrict__ rms_w,
               const float* __restrict__ b_res,
               const float* __restrict__ W_out,
               const float* __restrict__ b_out,
               float* __restrict__ out,
               int n, int ntiles)
{
    extern __shared__ char smem[];
    float* rsum   = (float*)(smem + OFF_RS);      // [128][4]
    float* win_s  = (float*)(smem + OFF_CST);     // 384
    float* bin_s  = win_s + 384;                  // 128
    float* rws_s  = bin_s + 128;                  // 512
    float* bbs_s  = rws_s + 512;                  // 512
    float* wout_s = bbs_s + 512;                  // 128
    float* xs_all = (float*)(smem + OFF_XS);      // [2][384]

    const int t      = threadIdx.x;
    const int warp   = t >> 5;
    const int lane   = t & 31;
    const int gid    = lane >> 2;
    const int tig    = lane & 3;
    const int warp_m = warp >> 2;       // 0..1 -> half id
    const int warp_n = warp & 3;
    const int m0     = warp_m * 64;
    const int n0w    = warp_n * 32;
    const int tid128 = t & 127;
    const int barid  = 1 + warp_m;
    const int wn2    = warp_n * 2;      // own k-chunk base

    const uint32_t wbase = smem_u32(smem + OFF_W);
    const uint32_t gbase = smem_u32(smem + OFF_G);
    const uint32_t xbase = smem_u32(xs_all);

    // ---- Stage consts once
    for (int i = t; i < 384; i += THREADS) win_s[i] = W_in[i];
    for (int i = t; i < 128; i += THREADS) {
        bin_s[i]  = b_in[i];
        wout_s[i] = W_out[i];
    }
    for (int i = t; i < 512; i += THREADS) {
        rws_s[i] = rms_w[i];
        bbs_s[i] = b_res[i];
    }
    // ---- Stage ALL 4 weight tiles once (bf16, 16B chunks)
    #pragma unroll
    for (int it = 0; it < 32; it++) {
        int i   = t + it * THREADS;     // 0..8191
        int nrg = i >> 4;               // blk*128 + row
        int kc  = i & 15;
        CP_ASYNC16(wbase + (uint32_t)(nrg * PITCHH + kc * 8) * 2,
                   g_wbf + nrg * HID + kc * 8);
    }
    CP_COMMIT;
    CP_WAIT0;
    __syncthreads();   // consts + W visible CTA-wide

    const float bout = b_out[0];

    // ldmatrix lane addresses (fixed)
    const uint32_t a_off = ((uint32_t)(m0 + (lane & 15)) * PITCHH
                           + (uint32_t)(lane >> 4) * 8) * 2;
    const int b_row = n0w + ((lane >> 4) * 8) + (lane & 7);
    const uint32_t b_off = ((uint32_t)b_row * PITCHH
                            + (uint32_t)(((lane >> 3) & 1) * 8)) * 2;

    bool pf_next = false;
    int  buf     = 0;

    for (int tile = blockIdx.x; tile < ntiles; tile += NSM, buf ^= 1) {
        const int row0 = tile * 128;
        float* xsb = xs_all + buf * 384;

        if (pf_next) {
            CP_WAIT0;
        } else {
            for (int i = tid128; i < 192; i += 128) {
                int idx = m0 * 3 + i;
                long long gi = (long long)row0 * 3 + idx;
                xsb[idx] = (gi < 3LL * n) ? x[gi] : 0.0f;
            }
        }
        BAR_HALF(barid);

        // ---- In-projection into fragment registers
        float hv[64];
        {
            float wc[8][3], bc[8];
            #pragma unroll
            for (int nt = 0; nt < 4; nt++) {
                int c0 = n0w + nt * 8 + 2 * tig;
                #pragma unroll
                for (int k = 0; k < 3; k++) {
                    wc[nt * 2 + 0][k] = win_s[c0 * 3 + k];
                    wc[nt * 2 + 1][k] = win_s[(c0 + 1) * 3 + k];
                }
                bc[nt * 2 + 0] = bin_s[c0];
                bc[nt * 2 + 1] = bin_s[c0 + 1];
            }
            #pragma unroll
            for (int mt = 0; mt < 4; mt++) {
                int r0 = m0 + mt * 16 + gid;
                float a0 = xsb[r0 * 3], a1 = xsb[r0 * 3 + 1], a2 = xsb[r0 * 3 + 2];
                float d0 = xsb[(r0 + 8) * 3], d1 = xsb[(r0 + 8) * 3 + 1], d2 = xsb[(r0 + 8) * 3 + 2];
                #pragma unroll
                for (int nt = 0; nt < 4; nt++) {
                    #pragma unroll
                    for (int p = 0; p < 2; p++) {
                        float* w = wc[nt * 2 + p];
                        hv[(mt * 4 + nt) * 4 + p] =
                            fmaf(a2, w[2], fmaf(a1, w[1], fmaf(a0, w[0], bc[nt * 2 + p])));
                        hv[(mt * 4 + nt) * 4 + 2 + p] =
                            fmaf(d2, w[2], fmaf(d1, w[1], fmaf(d0, w[0], bc[nt * 2 + p])));
                    }
                }
            }
        }

        // ---- Residual blocks
        for (int b = 0; b < NBLK; b++) {
            // rms partials into half-private rsum rows
            #pragma unroll
            for (int mt = 0; mt < 4; mt++) {
                float p0 = 0.f, p1 = 0.f;
                #pragma unroll
                for (int nt = 0; nt < 4; nt++) {
                    float e0 = hv[(mt*4+nt)*4+0], e1 = hv[(mt*4+nt)*4+1];
                    float e2 = hv[(mt*4+nt)*4+2], e3 = hv[(mt*4+nt)*4+3];
                    p0 = fmaf(e0, e0, fmaf(e1, e1, p0));
                    p1 = fmaf(e2, e2, fmaf(e3, e3, p1));
                }
                p0 += __shfl_xor_sync(0xffffffffu, p0, 1);
                p0 += __shfl_xor_sync(0xffffffffu, p0, 2);
                p1 += __shfl_xor_sync(0xffffffffu, p1, 1);
                p1 += __shfl_xor_sync(0xffffffffu, p1, 2);
                if (tig == 0) {
                    int r0 = m0 + mt * 16 + gid;
                    rsum[r0 * 4 + warp_n]       = p0;
                    rsum[(r0 + 8) * 4 + warp_n] = p1;
                }
            }
            BAR_HALF(barid);   // [A] rowsum visible; half's g rows free

            // scales + quantize to bf16; keep packed own-fragments in gq
            uint32_t gq[2][4][4];   // [own-k half][mt][a-reg]
            #pragma unroll
            for (int mt = 0; mt < 4; mt++) {
                int r0 = m0 + mt * 16 + gid;
                float4 s0 = *(const float4*)&rsum[r0 * 4];
                float4 s1 = *(const float4*)&rsum[(r0 + 8) * 4];
                float sc0 = rsqrtf((s0.x + s0.y + s0.z + s0.w) * (1.0f / HID) + RMS_EPS);
                float sc1 = rsqrtf((s1.x + s1.y + s1.z + s1.w) * (1.0f / HID) + RMS_EPS);
                #pragma unroll
                for (int nt = 0; nt < 4; nt++) {
                    int c0 = n0w + nt * 8 + 2 * tig;
                    float2 rw = *(const float2*)&rws_s[b * HID + c0];
                    uint32_t v0 = bf16x2(hv[(mt*4+nt)*4+0] * sc0 * rw.x,
                                         hv[(mt*4+nt)*4+1] * sc0 * rw.y);
                    uint32_t v1 = bf16x2(hv[(mt*4+nt)*4+2] * sc1 * rw.x,
                                         hv[(mt*4+nt)*4+3] * sc1 * rw.y);
                    gq[nt >> 1][mt][(nt & 1) * 2 + 0] = v0;
                    gq[nt >> 1][mt][(nt & 1) * 2 + 1] = v1;
                    asm volatile("st.shared.b32 [%0], %1;"
                        :: "r"(gbase + (uint32_t)(r0 * PITCHH + c0) * 2), "r"(v0) : "memory");
                    asm volatile("st.shared.b32 [%0], %1;"
                        :: "r"(gbase + (uint32_t)((r0 + 8) * PITCHH + c0) * 2), "r"(v1) : "memory");
                }
            }

            // Issue next-tile x prefetch EARLY (block 0, before GEMMs) so the
            // L2 flight hides under both GEMM phases.
            if (b == 0) {
                int nxt = tile + NSM;
                if (nxt < ntiles && (long long)(nxt + 1) * 128 <= (long long)n) {
                    if (tid128 < 48) {
                        uint32_t dst = xbase + (uint32_t)((buf ^ 1) * 1536 + m0 * 12
                                                          + tid128 * 16);
                        const char* src = (const char*)x + (long long)nxt * 1536
                                          + m0 * 12 + tid128 * 16;
                        CP_ASYNC16(dst, src);
                    }
                    CP_COMMIT;
                    pf_next = true;
                } else {
                    pf_next = false;
                }
            }

            // Early GEMM: own k-chunks (A from registers, B resident) —
            // issued BEFORE the barrier to fill its shadow.
            float acc[4][4][4];
            #pragma unroll
            for (int mt = 0; mt < 4; mt++)
                #pragma unroll
                for (int nt = 0; nt < 4; nt++) {
                    acc[mt][nt][0] = 0.f; acc[mt][nt][1] = 0.f;
                    acc[mt][nt][2] = 0.f; acc[mt][nt][3] = 0.f;
                }
            const uint32_t a_base = gbase + a_off;
            const uint32_t b_base = wbase + (uint32_t)b * TILE_HB + b_off;
            #pragma unroll
            for (int hk = 0; hk < 2; hk++) {
                const uint32_t koff = (uint32_t)(wn2 + hk) * 32;
                uint32_t bf[4][2];
                #pragma unroll
                for (int np = 0; np < 2; np++)
                    LDMATRIX_X4(bf[np*2][0], bf[np*2][1], bf[np*2+1][0], bf[np*2+1][1],
                                b_base + (uint32_t)np * (16 * PITCHH * 2) + koff);
                #pragma unroll
                for (int nt = 0; nt < 4; nt++)
                    #pragma unroll
                    for (int mt = 0; mt < 4; mt++)
                        MMA_BF16(acc[mt][nt],
                                 gq[hk][mt][0], gq[hk][mt][1],
                                 gq[hk][mt][2], gq[hk][mt][3],
                                 bf[nt][0], bf[nt][1]);
            }
            BAR_HALF(barid);   // [B] half's g rows visible

            // Late GEMM: remaining 6 k-chunks (A via ldmatrix)
            #pragma unroll
            for (int j = 0; j < 6; j++) {
                const int ks = j + ((j >= wn2) ? 2 : 0);
                const uint32_t koff = (uint32_t)ks * 32;
                uint32_t a[4][4];
                #pragma unroll
                for (int mt = 0; mt < 4; mt++)
                    LDMATRIX_X4(a[mt][0], a[mt][1], a[mt][2], a[mt][3],
                                a_base + (uint32_t)mt * (16 * PITCHH * 2) + koff);
                uint32_t bf[4][2];
                #pragma unroll
                for (int np = 0; np < 2; np++)
                    LDMATRIX_X4(bf[np*2][0], bf[np*2][1], bf[np*2+1][0], bf[np*2+1][1],
                                b_base + (uint32_t)np * (16 * PITCHH * 2) + koff);
                #pragma unroll
                for (int nt = 0; nt < 4; nt++)
                    #pragma unroll
                    for (int mt = 0; mt < 4; mt++)
                        MMA_BF16(acc[mt][nt],
                                 a[mt][0], a[mt][1], a[mt][2], a[mt][3],
                                 bf[nt][0], bf[nt][1]);
            }

            // residual: h += relu(acc + bias)
            #pragma unroll
            for (int nt = 0; nt < 4; nt++) {
                int c0 = n0w + nt * 8 + 2 * tig;
                float2 bias = *(const float2*)&bbs_s[b * HID + c0];
                #pragma unroll
                for (int mt = 0; mt < 4; mt++) {
                    hv[(mt*4+nt)*4+0] += fmaxf(acc[mt][nt][0] + bias.x, 0.0f);
                    hv[(mt*4+nt)*4+1] += fmaxf(acc[mt][nt][1] + bias.y, 0.0f);
                    hv[(mt*4+nt)*4+2] += fmaxf(acc[mt][nt][2] + bias.x, 0.0f);
                    hv[(mt*4+nt)*4+3] += fmaxf(acc[mt][nt][3] + bias.y, 0.0f);
                }
            }
        }

        // ---- Output projection (per-half reduction)
        #pragma unroll
        for (int mt = 0; mt < 4; mt++) {
            float o0 = 0.f, o1 = 0.f;
            #pragma unroll
            for (int nt = 0; nt < 4; nt++) {
                int c0 = n0w + nt * 8 + 2 * tig;
                float2 w = *(const float2*)&wout_s[c0];
                o0 = fmaf(hv[(mt*4+nt)*4+0], w.x, fmaf(hv[(mt*4+nt)*4+1], w.y, o0));
                o1 = fmaf(hv[(mt*4+nt)*4+2], w.x, fmaf(hv[(mt*4+nt)*4+3], w.y, o1));
            }
            o0 += __shfl_xor_sync(0xffffffffu, o0, 1);
            o0 += __shfl_xor_sync(0xffffffffu, o0, 2);
            o1 += __shfl_xor_sync(0xffffffffu, o1, 1);
            o1 += __shfl_xor_sync(0xffffffffu, o1, 2);
            if (tig == 0) {
                int r0 = m0 + mt * 16 + gid;
                rsum[r0 * 4 + warp_n]       = o0;
                rsum[(r0 + 8) * 4 + warp_n] = o1;
            }
        }
        BAR_HALF(barid);
        if (tid128 < 64) {
            int r = m0 + tid128;
            long long gr = (long long)row0 + r;
            if (gr < n) {
                float4 s = *(const float4*)&rsum[r * 4];
                float lg = s.x + s.y + s.z + s.w + bout;
                float e = __expf(lg);
                out[gr] = e;
                atomicAdd(&g_ssum[ids[gr]], e);
            }
        }
    }
}

// ---------------------------------------------------------------------------
// Normalize: out[i] /= ssum[ids[i]], 8 elements per thread
// ---------------------------------------------------------------------------
__global__ void seg_norm_kernel(const int* __restrict__ ids,
                                float* __restrict__ out, int n)
{
    int base = (blockIdx.x * blockDim.x + threadIdx.x) * 8;
    if (base + 7 < n) {
        #pragma unroll
        for (int q = 0; q < 2; q++) {
            int i = base + q * 4;
            int4   s = *(const int4*)&ids[i];
            float4 v = *(float4*)&out[i];
            v.x /= g_ssum[s.x];
            v.y /= g_ssum[s.y];
            v.z /= g_ssum[s.z];
            v.w /= g_ssum[s.w];
            *(float4*)&out[i] = v;
        }
    } else {
        for (int j = base; j < n; j++) out[j] /= g_ssum[ids[j]];
    }
}

// ---------------------------------------------------------------------------
extern "C" void kernel_launch(void* const* d_in, const int* in_sizes, int n_in,
                              void* d_out, int out_size)
{
    const float* x     = (const float*)d_in[0];
    const int*   ids   = (const int*)  d_in[1];
    const float* W_in  = (const float*)d_in[2];
    const float* b_in  = (const float*)d_in[3];
    const float* rms_w = (const float*)d_in[4];
    const float* W_res = (const float*)d_in[5];
    const float* b_res = (const float*)d_in[6];
    const float* W_out = (const float*)d_in[7];
    const float* b_out = (const float*)d_in[8];
    float* out = (float*)d_out;
    const int n = in_sizes[1];
    const int ntiles = (n + 127) / 128;

    cudaFuncSetAttribute(mlp_mma_kernel,
                         cudaFuncAttributeMaxDynamicSharedMemorySize,
                         SMEM_TOTAL);

    prep_kernel<<<(NSEG / 4 + 255) / 256, 256>>>(W_res);
    mlp_mma_kernel<<<NSM, THREADS, SMEM_TOTAL>>>(
        x, ids, W_in, b_in, rms_w, b_res, W_out, b_out, out, n, ntiles);
    seg_norm_kernel<<<((n + 7) / 8 + 255) / 256, 256>>>(ids, out, n);
}

// round 11
// speedup vs baseline: 2.6252x; 1.0319x over previous
#include <cuda_runtime.h>
#include <cuda_bf16.h>
#include <cstdint>
#include <math.h>

// Problem constants
#define NSEG 500000
#define HID 128
#define NBLK 4
#define THREADS 256
#define NSM 152              // persistent grid size (GB300 has 152 SMs)
#define PITCHH 136           // halfs per bf16 tile row (ldmatrix-conflict-free pad)
#define RMS_EPS 1.1920929e-07f

#define TILE_HB (128 * PITCHH * 2)          // bytes per 128x128 bf16 tile (34816)
#define OFF_W   0                            // 4 weight tiles
#define OFF_G   (4 * TILE_HB)                // 1 g tile (half-private rows)
#define OFF_RS  (5 * TILE_HB)                // rowsum[128][4] floats (2048 B)
#define OFF_CST (OFF_RS + 2048)              // consts: 1664 floats (6656 B)
#define OFF_XS  (OFF_CST + 6656)             // xs double buffer 2*384 floats (3072 B)
#define SMEM_TOTAL (OFF_XS + 3072)

// Scratch (device globals — no allocation allowed)
__device__ float         g_ssum[NSEG];
__device__ __nv_bfloat16 g_wbf[NBLK * HID * HID];

__device__ __forceinline__ uint32_t smem_u32(const void* p) {
    uint32_t a;
    asm("{ .reg .u64 t; cvta.to.shared.u64 t, %1; cvt.u32.u64 %0, t; }"
        : "=r"(a) : "l"(p));
    return a;
}
__device__ __forceinline__ uint32_t bf16x2(float lo, float hi) {
    uint32_t r;
    asm("cvt.rn.bf16x2.f32 %0, %1, %2;" : "=r"(r) : "f"(hi), "f"(lo));
    return r;
}

#define CP_ASYNC16(dst, src) \
    asm volatile("cp.async.cg.shared.global [%0], [%1], 16;" \
                 :: "r"(dst), "l"(src) : "memory")
#define CP_COMMIT asm volatile("cp.async.commit_group;" ::: "memory")
#define CP_WAIT0  asm volatile("cp.async.wait_group 0;" ::: "memory")

// Half-CTA named barrier (128 threads each; ids 1 and 2)
#define BAR_HALF(id) asm volatile("bar.sync %0, 128;" :: "r"(id) : "memory")

#define LDMATRIX_X4(r0, r1, r2, r3, addr) \
    asm volatile("ldmatrix.sync.aligned.m8n8.x4.shared.b16 {%0,%1,%2,%3}, [%4];" \
                 : "=r"(r0), "=r"(r1), "=r"(r2), "=r"(r3) : "r"(addr))

#define MMA_BF16(d, a0, a1, a2, a3, b0, b1) \
    asm volatile("mma.sync.aligned.m16n8k16.row.col.f32.bf16.bf16.f32 " \
        "{%0,%1,%2,%3}, {%4,%5,%6,%7}, {%8,%9}, {%0,%1,%2,%3};" \
        : "+f"((d)[0]), "+f"((d)[1]), "+f"((d)[2]), "+f"((d)[3]) \
        : "r"(a0), "r"(a1), "r"(a2), "r"(a3), "r"(b0), "r"(b1))

// ---------------------------------------------------------------------------
// Prep (vectorized): zero segment sums (float4) + convert W to bf16 (float4
// -> 2x bf16x2 as uint2). One launch, small grid.
// ---------------------------------------------------------------------------
__global__ void prep_kernel(const float* __restrict__ W_res) {
    int i = blockIdx.x * blockDim.x + threadIdx.x;
    if (i < NSEG / 4)
        ((float4*)g_ssum)[i] = make_float4(0.f, 0.f, 0.f, 0.f);
    if (i < (NBLK * HID * HID) / 4) {
        float4 v = ((const float4*)W_res)[i];
        uint2 o;
        o.x = bf16x2(v.x, v.y);
        o.y = bf16x2(v.z, v.w);
        ((uint2*)g_wbf)[i] = o;
    }
}

// ---------------------------------------------------------------------------
// Persistent fused MLP (bf16 mma). h in fragment registers end-to-end.
// Two free-running 64-row halves. Own-A-fragment shortcut: k-chunks
// 2*warp_n, 2*warp_n+1 use register A operands, issued pre-barrier.
// ---------------------------------------------------------------------------
__global__ void __launch_bounds__(THREADS, 1)
mlp_mma_kernel(const float* __restrict__ x,
               const int*   __restrict__ ids,
               const float* __restrict__ W_in,
               const float* __restrict__ b_in,
               const float* __restrict__ rms_w,
               const float* __restrict__ b_res,
               const float* __restrict__ W_out,
               const float* __restrict__ b_out,
               float* __restrict__ out,
               int n, int ntiles)
{
    extern __shared__ char smem[];
    float* rsum   = (float*)(smem + OFF_RS);      // [128][4]
    float* win_s  = (float*)(smem + OFF_CST);     // 384
    float* bin_s  = win_s + 384;                  // 128
    float* rws_s  = bin_s + 128;                  // 512
    float* bbs_s  = rws_s + 512;                  // 512
    float* wout_s = bbs_s + 512;                  // 128
    float* xs_all = (float*)(smem + OFF_XS);      // [2][384]

    const int t      = threadIdx.x;
    const int warp   = t >> 5;
    const int lane   = t & 31;
    const int gid    = lane >> 2;
    const int tig    = lane & 3;
    const int warp_m = warp >> 2;       // 0..1 -> half id
    const int warp_n = warp & 3;
    const int m0     = warp_m * 64;
    const int n0w    = warp_n * 32;
    const int tid128 = t & 127;
    const int barid  = 1 + warp_m;
    const int wn2    = warp_n * 2;      // own k-chunk base

    const uint32_t wbase = smem_u32(smem + OFF_W);
    const uint32_t gbase = smem_u32(smem + OFF_G);
    const uint32_t xbase = smem_u32(xs_all);

    // ---- Stage consts once
    for (int i = t; i < 384; i += THREADS) win_s[i] = W_in[i];
    for (int i = t; i < 128; i += THREADS) {
        bin_s[i]  = b_in[i];
        wout_s[i] = W_out[i];
    }
    for (int i = t; i < 512; i += THREADS) {
        rws_s[i] = rms_w[i];
        bbs_s[i] = b_res[i];
    }
    // ---- Stage ALL 4 weight tiles once (bf16, 16B chunks)
    #pragma unroll
    for (int it = 0; it < 32; it++) {
        int i   = t + it * THREADS;     // 0..8191
        int nrg = i >> 4;               // blk*128 + row
        int kc  = i & 15;
        CP_ASYNC16(wbase + (uint32_t)(nrg * PITCHH + kc * 8) * 2,
                   g_wbf + nrg * HID + kc * 8);
    }
    CP_COMMIT;
    CP_WAIT0;
    __syncthreads();   // consts + W visible CTA-wide

    const float bout = b_out[0];

    // ldmatrix lane addresses (fixed)
    const uint32_t a_off = ((uint32_t)(m0 + (lane & 15)) * PITCHH
                           + (uint32_t)(lane >> 4) * 8) * 2;
    const int b_row = n0w + ((lane >> 4) * 8) + (lane & 7);
    const uint32_t b_off = ((uint32_t)b_row * PITCHH
                            + (uint32_t)(((lane >> 3) & 1) * 8)) * 2;

    bool pf_next = false;
    int  buf     = 0;

    for (int tile = blockIdx.x; tile < ntiles; tile += NSM, buf ^= 1) {
        const int row0 = tile * 128;
        float* xsb = xs_all + buf * 384;

        if (pf_next) {
            CP_WAIT0;
        } else {
            for (int i = tid128; i < 192; i += 128) {
                int idx = m0 * 3 + i;
                long long gi = (long long)row0 * 3 + idx;
                xsb[idx] = (gi < 3LL * n) ? x[gi] : 0.0f;
            }
        }
        BAR_HALF(barid);

        // ---- In-projection into fragment registers
        float hv[64];
        {
            float wc[8][3], bc[8];
            #pragma unroll
            for (int nt = 0; nt < 4; nt++) {
                int c0 = n0w + nt * 8 + 2 * tig;
                #pragma unroll
                for (int k = 0; k < 3; k++) {
                    wc[nt * 2 + 0][k] = win_s[c0 * 3 + k];
                    wc[nt * 2 + 1][k] = win_s[(c0 + 1) * 3 + k];
                }
                bc[nt * 2 + 0] = bin_s[c0];
                bc[nt * 2 + 1] = bin_s[c0 + 1];
            }
            #pragma unroll
            for (int mt = 0; mt < 4; mt++) {
                int r0 = m0 + mt * 16 + gid;
                float a0 = xsb[r0 * 3], a1 = xsb[r0 * 3 + 1], a2 = xsb[r0 * 3 + 2];
                float d0 = xsb[(r0 + 8) * 3], d1 = xsb[(r0 + 8) * 3 + 1], d2 = xsb[(r0 + 8) * 3 + 2];
                #pragma unroll
                for (int nt = 0; nt < 4; nt++) {
                    #pragma unroll
                    for (int p = 0; p < 2; p++) {
                        float* w = wc[nt * 2 + p];
                        hv[(mt * 4 + nt) * 4 + p] =
                            fmaf(a2, w[2], fmaf(a1, w[1], fmaf(a0, w[0], bc[nt * 2 + p])));
                        hv[(mt * 4 + nt) * 4 + 2 + p] =
                            fmaf(d2, w[2], fmaf(d1, w[1], fmaf(d0, w[0], bc[nt * 2 + p])));
                    }
                }
            }
        }

        // ---- Residual blocks
        for (int b = 0; b < NBLK; b++) {
            // rms partials into half-private rsum rows
            #pragma unroll
            for (int mt = 0; mt < 4; mt++) {
                float p0 = 0.f, p1 = 0.f;
                #pragma unroll
                for (int nt = 0; nt < 4; nt++) {
                    float e0 = hv[(mt*4+nt)*4+0], e1 = hv[(mt*4+nt)*4+1];
                    float e2 = hv[(mt*4+nt)*4+2], e3 = hv[(mt*4+nt)*4+3];
                    p0 = fmaf(e0, e0, fmaf(e1, e1, p0));
                    p1 = fmaf(e2, e2, fmaf(e3, e3, p1));
                }
                p0 += __shfl_xor_sync(0xffffffffu, p0, 1);
                p0 += __shfl_xor_sync(0xffffffffu, p0, 2);
                p1 += __shfl_xor_sync(0xffffffffu, p1, 1);
                p1 += __shfl_xor_sync(0xffffffffu, p1, 2);
                if (tig == 0) {
                    int r0 = m0 + mt * 16 + gid;
                    rsum[r0 * 4 + warp_n]       = p0;
                    rsum[(r0 + 8) * 4 + warp_n] = p1;
                }
            }
            BAR_HALF(barid);   // [A] rowsum visible; half's g rows free

            // scales + quantize to bf16; keep packed own-fragments in gq
            uint32_t gq[2][4][4];   // [own-k half][mt][a-reg]
            #pragma unroll
            for (int mt = 0; mt < 4; mt++) {
                int r0 = m0 + mt * 16 + gid;
                float4 s0 = *(const float4*)&rsum[r0 * 4];
                float4 s1 = *(const float4*)&rsum[(r0 + 8) * 4];
                float sc0 = rsqrtf((s0.x + s0.y + s0.z + s0.w) * (1.0f / HID) + RMS_EPS);
                float sc1 = rsqrtf((s1.x + s1.y + s1.z + s1.w) * (1.0f / HID) + RMS_EPS);
                #pragma unroll
                for (int nt = 0; nt < 4; nt++) {
                    int c0 = n0w + nt * 8 + 2 * tig;
                    float2 rw = *(const float2*)&rws_s[b * HID + c0];
                    uint32_t v0 = bf16x2(hv[(mt*4+nt)*4+0] * sc0 * rw.x,
                                         hv[(mt*4+nt)*4+1] * sc0 * rw.y);
                    uint32_t v1 = bf16x2(hv[(mt*4+nt)*4+2] * sc1 * rw.x,
                                         hv[(mt*4+nt)*4+3] * sc1 * rw.y);
                    gq[nt >> 1][mt][(nt & 1) * 2 + 0] = v0;
                    gq[nt >> 1][mt][(nt & 1) * 2 + 1] = v1;
                    asm volatile("st.shared.b32 [%0], %1;"
                        :: "r"(gbase + (uint32_t)(r0 * PITCHH + c0) * 2), "r"(v0) : "memory");
                    asm volatile("st.shared.b32 [%0], %1;"
                        :: "r"(gbase + (uint32_t)((r0 + 8) * PITCHH + c0) * 2), "r"(v1) : "memory");
                }
            }

            // Issue next-tile x prefetch EARLY (block 0, before GEMMs)
            if (b == 0) {
                int nxt = tile + NSM;
                if (nxt < ntiles && (long long)(nxt + 1) * 128 <= (long long)n) {
                    if (tid128 < 48) {
                        uint32_t dst = xbase + (uint32_t)((buf ^ 1) * 1536 + m0 * 12
                                                          + tid128 * 16);
                        const char* src = (const char*)x + (long long)nxt * 1536
                                          + m0 * 12 + tid128 * 16;
                        CP_ASYNC16(dst, src);
                    }
                    CP_COMMIT;
                    pf_next = true;
                } else {
                    pf_next = false;
                }
            }

            // Early GEMM: own k-chunks (A from registers, B resident) —
            // issued BEFORE the barrier to fill its shadow.
            float acc[4][4][4];
            #pragma unroll
            for (int mt = 0; mt < 4; mt++)
                #pragma unroll
                for (int nt = 0; nt < 4; nt++) {
                    acc[mt][nt][0] = 0.f; acc[mt][nt][1] = 0.f;
                    acc[mt][nt][2] = 0.f; acc[mt][nt][3] = 0.f;
                }
            const uint32_t a_base = gbase + a_off;
            const uint32_t b_base = wbase + (uint32_t)b * TILE_HB + b_off;
            #pragma unroll
            for (int hk = 0; hk < 2; hk++) {
                const uint32_t koff = (uint32_t)(wn2 + hk) * 32;
                uint32_t bf[4][2];
                #pragma unroll
                for (int np = 0; np < 2; np++)
                    LDMATRIX_X4(bf[np*2][0], bf[np*2][1], bf[np*2+1][0], bf[np*2+1][1],
                                b_base + (uint32_t)np * (16 * PITCHH * 2) + koff);
                #pragma unroll
                for (int nt = 0; nt < 4; nt++)
                    #pragma unroll
                    for (int mt = 0; mt < 4; mt++)
                        MMA_BF16(acc[mt][nt],
                                 gq[hk][mt][0], gq[hk][mt][1],
                                 gq[hk][mt][2], gq[hk][mt][3],
                                 bf[nt][0], bf[nt][1]);
            }
            BAR_HALF(barid);   // [B] half's g rows visible

            // Late GEMM: remaining 6 k-chunks (A via ldmatrix)
            #pragma unroll
            for (int j = 0; j < 6; j++) {
                const int ks = j + ((j >= wn2) ? 2 : 0);
                const uint32_t koff = (uint32_t)ks * 32;
                uint32_t a[4][4];
                #pragma unroll
                for (int mt = 0; mt < 4; mt++)
                    LDMATRIX_X4(a[mt][0], a[mt][1], a[mt][2], a[mt][3],
                                a_base + (uint32_t)mt * (16 * PITCHH * 2) + koff);
                uint32_t bf[4][2];
                #pragma unroll
                for (int np = 0; np < 2; np++)
                    LDMATRIX_X4(bf[np*2][0], bf[np*2][1], bf[np*2+1][0], bf[np*2+1][1],
                                b_base + (uint32_t)np * (16 * PITCHH * 2) + koff);
                #pragma unroll
                for (int nt = 0; nt < 4; nt++)
                    #pragma unroll
                    for (int mt = 0; mt < 4; mt++)
                        MMA_BF16(acc[mt][nt],
                                 a[mt][0], a[mt][1], a[mt][2], a[mt][3],
                                 bf[nt][0], bf[nt][1]);
            }

            // residual: h += relu(acc + bias)
            #pragma unroll
            for (int nt = 0; nt < 4; nt++) {
                int c0 = n0w + nt * 8 + 2 * tig;
                float2 bias = *(const float2*)&bbs_s[b * HID + c0];
                #pragma unroll
                for (int mt = 0; mt < 4; mt++) {
                    hv[(mt*4+nt)*4+0] += fmaxf(acc[mt][nt][0] + bias.x, 0.0f);
                    hv[(mt*4+nt)*4+1] += fmaxf(acc[mt][nt][1] + bias.y, 0.0f);
                    hv[(mt*4+nt)*4+2] += fmaxf(acc[mt][nt][2] + bias.x, 0.0f);
                    hv[(mt*4+nt)*4+3] += fmaxf(acc[mt][nt][3] + bias.y, 0.0f);
                }
            }
        }

        // ---- Output projection (per-half reduction)
        #pragma unroll
        for (int mt = 0; mt < 4; mt++) {
            float o0 = 0.f, o1 = 0.f;
            #pragma unroll
            for (int nt = 0; nt < 4; nt++) {
                int c0 = n0w + nt * 8 + 2 * tig;
                float2 w = *(const float2*)&wout_s[c0];
                o0 = fmaf(hv[(mt*4+nt)*4+0], w.x, fmaf(hv[(mt*4+nt)*4+1], w.y, o0));
                o1 = fmaf(hv[(mt*4+nt)*4+2], w.x, fmaf(hv[(mt*4+nt)*4+3], w.y, o1));
            }
            o0 += __shfl_xor_sync(0xffffffffu, o0, 1);
            o0 += __shfl_xor_sync(0xffffffffu, o0, 2);
            o1 += __shfl_xor_sync(0xffffffffu, o1, 1);
            o1 += __shfl_xor_sync(0xffffffffu, o1, 2);
            if (tig == 0) {
                int r0 = m0 + mt * 16 + gid;
                rsum[r0 * 4 + warp_n]       = o0;
                rsum[(r0 + 8) * 4 + warp_n] = o1;
            }
        }
        BAR_HALF(barid);
        if (tid128 < 64) {
            int r = m0 + tid128;
            long long gr = (long long)row0 + r;
            if (gr < n) {
                float4 s = *(const float4*)&rsum[r * 4];
                float lg = s.x + s.y + s.z + s.w + bout;
                float e = __expf(lg);
                out[gr] = e;
                atomicAdd(&g_ssum[ids[gr]], e);
            }
        }
    }
}

// ---------------------------------------------------------------------------
// Normalize: out[i] /= ssum[ids[i]], 8 elements per thread, fast divide
// ---------------------------------------------------------------------------
__global__ void seg_norm_kernel(const int* __restrict__ ids,
                                float* __restrict__ out, int n)
{
    int base = (blockIdx.x * blockDim.x + threadIdx.x) * 8;
    if (base + 7 < n) {
        #pragma unroll
        for (int q = 0; q < 2; q++) {
            int i = base + q * 4;
            int4   s = *(const int4*)&ids[i];
            float4 v = *(float4*)&out[i];
            v.x = __fdividef(v.x, g_ssum[s.x]);
            v.y = __fdividef(v.y, g_ssum[s.y]);
            v.z = __fdividef(v.z, g_ssum[s.z]);
            v.w = __fdividef(v.w, g_ssum[s.w]);
            *(float4*)&out[i] = v;
        }
    } else {
        for (int j = base; j < n; j++) out[j] = __fdividef(out[j], g_ssum[ids[j]]);
    }
}

// ---------------------------------------------------------------------------
extern "C" void kernel_launch(void* const* d_in, const int* in_sizes, int n_in,
                              void* d_out, int out_size)
{
    const float* x     = (const float*)d_in[0];
    const int*   ids   = (const int*)  d_in[1];
    const float* W_in  = (const float*)d_in[2];
    const float* b_in  = (const float*)d_in[3];
    const float* rms_w = (const float*)d_in[4];
    const float* W_res = (const float*)d_in[5];
    const float* b_res = (const float*)d_in[6];
    const float* W_out = (const float*)d_in[7];
    const float* b_out = (const float*)d_in[8];
    float* out = (float*)d_out;
    const int n = in_sizes[1];
    const int ntiles = (n + 127) / 128;

    cudaFuncSetAttribute(mlp_mma_kernel,
                         cudaFuncAttributeMaxDynamicSharedMemorySize,
                         SMEM_TOTAL);

    prep_kernel<<<(NSEG / 4 + 255) / 256, 256>>>(W_res);
    mlp_mma_kernel<<<NSM, THREADS, SMEM_TOTAL>>>(
        x, ids, W_in, b_in, rms_w, b_res, W_out, b_out, out, n, ntiles);
    seg_norm_kernel<<<((n + 7) / 8 + 255) / 256, 256>>>(ids, out, n);
}

// round 12
// speedup vs baseline: 2.7112x; 1.0327x over previous
#include <cuda_runtime.h>
#include <cuda_bf16.h>
#include <cstdint>
#include <math.h>

// Problem constants
#define NSEG 500000
#define HID 128
#define NBLK 4
#define THREADS 256
#define NSM 152              // persistent grid size (GB300 has 152 SMs)
#define PITCHH 136           // halfs per bf16 tile row (ldmatrix-conflict-free pad)
#define RMS_EPS 1.1920929e-07f

#define TILE_HB (128 * PITCHH * 2)          // bytes per 128x128 bf16 tile (34816)
#define OFF_W   0                            // 4 weight tiles
#define OFF_G   (4 * TILE_HB)                // 1 g tile (half-private rows)
#define OFF_RS  (5 * TILE_HB)                // rsum[2][128][4] floats (4096 B)
#define OFF_CST (OFF_RS + 4096)              // consts: 1664 floats (6656 B)
#define OFF_XS  (OFF_CST + 6656)             // xs double buffer 2*384 floats (3072 B)
#define SMEM_TOTAL (OFF_XS + 3072)

// Scratch (device globals — no allocation allowed)
__device__ float         g_ssum[NSEG];
__device__ __nv_bfloat16 g_wbf[NBLK * HID * HID];

__device__ __forceinline__ uint32_t smem_u32(const void* p) {
    uint32_t a;
    asm("{ .reg .u64 t; cvta.to.shared.u64 t, %1; cvt.u32.u64 %0, t; }"
        : "=r"(a) : "l"(p));
    return a;
}
__device__ __forceinline__ uint32_t bf16x2(float lo, float hi) {
    uint32_t r;
    asm("cvt.rn.bf16x2.f32 %0, %1, %2;" : "=r"(r) : "f"(hi), "f"(lo));
    return r;
}

#define CP_ASYNC16(dst, src) \
    asm volatile("cp.async.cg.shared.global [%0], [%1], 16;" \
                 :: "r"(dst), "l"(src) : "memory")
#define CP_COMMIT asm volatile("cp.async.commit_group;" ::: "memory")
#define CP_WAIT0  asm volatile("cp.async.wait_group 0;" ::: "memory")

// Half-CTA named barrier (128 threads each; ids 1 and 2)
#define BAR_HALF(id) asm volatile("bar.sync %0, 128;" :: "r"(id) : "memory")

#define LDMATRIX_X4(r0, r1, r2, r3, addr) \
    asm volatile("ldmatrix.sync.aligned.m8n8.x4.shared.b16 {%0,%1,%2,%3}, [%4];" \
                 : "=r"(r0), "=r"(r1), "=r"(r2), "=r"(r3) : "r"(addr))

#define MMA_BF16(d, a0, a1, a2, a3, b0, b1) \
    asm volatile("mma.sync.aligned.m16n8k16.row.col.f32.bf16.bf16.f32 " \
        "{%0,%1,%2,%3}, {%4,%5,%6,%7}, {%8,%9}, {%0,%1,%2,%3};" \
        : "+f"((d)[0]), "+f"((d)[1]), "+f"((d)[2]), "+f"((d)[3]) \
        : "r"(a0), "r"(a1), "r"(a2), "r"(a3), "r"(b0), "r"(b1))

// ---------------------------------------------------------------------------
// Prep (vectorized): zero segment sums (float4) + convert W to bf16.
// ---------------------------------------------------------------------------
__global__ void prep_kernel(const float* __restrict__ W_res) {
    int i = blockIdx.x * blockDim.x + threadIdx.x;
    if (i < NSEG / 4)
        ((float4*)g_ssum)[i] = make_float4(0.f, 0.f, 0.f, 0.f);
    if (i < (NBLK * HID * HID) / 4) {
        float4 v = ((const float4*)W_res)[i];
        uint2 o;
        o.x = bf16x2(v.x, v.y);
        o.y = bf16x2(v.z, v.w);
        ((uint2*)g_wbf)[i] = o;
    }
}

// ---------------------------------------------------------------------------
// Persistent fused MLP (bf16 mma). h in fragment registers end-to-end.
// rmsnorm scale applied POST-GEMM (per-row scalar commutes through the
// matmul), so quantize+gemm issue with no cross-warp dependency and each
// res block needs only ONE half-barrier. rsum double-buffered.
// ---------------------------------------------------------------------------
__global__ void __launch_bounds__(THREADS, 1)
mlp_mma_kernel(const float* __restrict__ x,
               const int*   __restrict__ ids,
               const float* __restrict__ W_in,
               const float* __restrict__ b_in,
               const float* __restrict__ rms_w,
               const float* __restrict__ b_res,
               const float* __restrict__ W_out,
               const float* __restrict__ b_out,
               float* __restrict__ out,
               int n, int ntiles)
{
    extern __shared__ char smem[];
    float* rsum   = (float*)(smem + OFF_RS);      // [2][128][4]
    float* win_s  = (float*)(smem + OFF_CST);     // 384
    float* bin_s  = win_s + 384;                  // 128
    float* rws_s  = bin_s + 128;                  // 512
    float* bbs_s  = rws_s + 512;                  // 512
    float* wout_s = bbs_s + 512;                  // 128
    float* xs_all = (float*)(smem + OFF_XS);      // [2][384]

    const int t      = threadIdx.x;
    const int warp   = t >> 5;
    const int lane   = t & 31;
    const int gid    = lane >> 2;
    const int tig    = lane & 3;
    const int warp_m = warp >> 2;       // 0..1 -> half id
    const int warp_n = warp & 3;
    const int m0     = warp_m * 64;
    const int n0w    = warp_n * 32;
    const int tid128 = t & 127;
    const int barid  = 1 + warp_m;
    const int wn2    = warp_n * 2;      // own k-chunk base

    const uint32_t wbase = smem_u32(smem + OFF_W);
    const uint32_t gbase = smem_u32(smem + OFF_G);
    const uint32_t xbase = smem_u32(xs_all);

    // ---- Stage consts once
    for (int i = t; i < 384; i += THREADS) win_s[i] = W_in[i];
    for (int i = t; i < 128; i += THREADS) {
        bin_s[i]  = b_in[i];
        wout_s[i] = W_out[i];
    }
    for (int i = t; i < 512; i += THREADS) {
        rws_s[i] = rms_w[i];
        bbs_s[i] = b_res[i];
    }
    // ---- Stage ALL 4 weight tiles once (bf16, 16B chunks)
    #pragma unroll
    for (int it = 0; it < 32; it++) {
        int i   = t + it * THREADS;     // 0..8191
        int nrg = i >> 4;               // blk*128 + row
        int kc  = i & 15;
        CP_ASYNC16(wbase + (uint32_t)(nrg * PITCHH + kc * 8) * 2,
                   g_wbf + nrg * HID + kc * 8);
    }
    CP_COMMIT;
    CP_WAIT0;
    __syncthreads();   // consts + W visible CTA-wide

    const float bout = b_out[0];

    // ldmatrix lane addresses (fixed)
    const uint32_t a_off = ((uint32_t)(m0 + (lane & 15)) * PITCHH
                           + (uint32_t)(lane >> 4) * 8) * 2;
    const int b_row = n0w + ((lane >> 4) * 8) + (lane & 7);
    const uint32_t b_off = ((uint32_t)b_row * PITCHH
                            + (uint32_t)(((lane >> 3) & 1) * 8)) * 2;

    bool pf_next = false;
    int  buf     = 0;

    for (int tile = blockIdx.x; tile < ntiles; tile += NSM, buf ^= 1) {
        const int row0 = tile * 128;
        float* xsb = xs_all + buf * 384;

        if (pf_next) {
            CP_WAIT0;
        } else {
            for (int i = tid128; i < 192; i += 128) {
                int idx = m0 * 3 + i;
                long long gi = (long long)row0 * 3 + idx;
                xsb[idx] = (gi < 3LL * n) ? x[gi] : 0.0f;
            }
        }
        BAR_HALF(barid);

        // ---- In-projection into fragment registers
        float hv[64];
        {
            float wc[8][3], bc[8];
            #pragma unroll
            for (int nt = 0; nt < 4; nt++) {
                int c0 = n0w + nt * 8 + 2 * tig;
                #pragma unroll
                for (int k = 0; k < 3; k++) {
                    wc[nt * 2 + 0][k] = win_s[c0 * 3 + k];
                    wc[nt * 2 + 1][k] = win_s[(c0 + 1) * 3 + k];
                }
                bc[nt * 2 + 0] = bin_s[c0];
                bc[nt * 2 + 1] = bin_s[c0 + 1];
            }
            #pragma unroll
            for (int mt = 0; mt < 4; mt++) {
                int r0 = m0 + mt * 16 + gid;
                float a0 = xsb[r0 * 3], a1 = xsb[r0 * 3 + 1], a2 = xsb[r0 * 3 + 2];
                float d0 = xsb[(r0 + 8) * 3], d1 = xsb[(r0 + 8) * 3 + 1], d2 = xsb[(r0 + 8) * 3 + 2];
                #pragma unroll
                for (int nt = 0; nt < 4; nt++) {
                    #pragma unroll
                    for (int p = 0; p < 2; p++) {
                        float* w = wc[nt * 2 + p];
                        hv[(mt * 4 + nt) * 4 + p] =
                            fmaf(a2, w[2], fmaf(a1, w[1], fmaf(a0, w[0], bc[nt * 2 + p])));
                        hv[(mt * 4 + nt) * 4 + 2 + p] =
                            fmaf(d2, w[2], fmaf(d1, w[1], fmaf(d0, w[0], bc[nt * 2 + p])));
                    }
                }
            }
        }

        // ---- Residual blocks (ONE barrier each)
        for (int b = 0; b < NBLK; b++) {
            float* rsb = rsum + (b & 1) * 512;   // double-buffered rowsum

            // rms partial sumsq -> rsb (overlaps quantize below)
            #pragma unroll
            for (int mt = 0; mt < 4; mt++) {
                float p0 = 0.f, p1 = 0.f;
                #pragma unroll
                for (int nt = 0; nt < 4; nt++) {
                    float e0 = hv[(mt*4+nt)*4+0], e1 = hv[(mt*4+nt)*4+1];
                    float e2 = hv[(mt*4+nt)*4+2], e3 = hv[(mt*4+nt)*4+3];
                    p0 = fmaf(e0, e0, fmaf(e1, e1, p0));
                    p1 = fmaf(e2, e2, fmaf(e3, e3, p1));
                }
                p0 += __shfl_xor_sync(0xffffffffu, p0, 1);
                p0 += __shfl_xor_sync(0xffffffffu, p0, 2);
                p1 += __shfl_xor_sync(0xffffffffu, p1, 1);
                p1 += __shfl_xor_sync(0xffffffffu, p1, 2);
                if (tig == 0) {
                    int r0 = m0 + mt * 16 + gid;
                    rsb[r0 * 4 + warp_n]       = p0;
                    rsb[(r0 + 8) * 4 + warp_n] = p1;
                }
            }

            // quantize g = bf16(h * rms_w) — NO row scale (applied post-GEMM);
            // straight from registers, no cross-warp dependency.
            uint32_t gq[2][4][4];   // [own-k half][mt][a-reg]
            #pragma unroll
            for (int mt = 0; mt < 4; mt++) {
                int r0 = m0 + mt * 16 + gid;
                #pragma unroll
                for (int nt = 0; nt < 4; nt++) {
                    int c0 = n0w + nt * 8 + 2 * tig;
                    float2 rw = *(const float2*)&rws_s[b * HID + c0];
                    uint32_t v0 = bf16x2(hv[(mt*4+nt)*4+0] * rw.x,
                                         hv[(mt*4+nt)*4+1] * rw.y);
                    uint32_t v1 = bf16x2(hv[(mt*4+nt)*4+2] * rw.x,
                                         hv[(mt*4+nt)*4+3] * rw.y);
                    gq[nt >> 1][mt][(nt & 1) * 2 + 0] = v0;
                    gq[nt >> 1][mt][(nt & 1) * 2 + 1] = v1;
                    asm volatile("st.shared.b32 [%0], %1;"
                        :: "r"(gbase + (uint32_t)(r0 * PITCHH + c0) * 2), "r"(v0) : "memory");
                    asm volatile("st.shared.b32 [%0], %1;"
                        :: "r"(gbase + (uint32_t)((r0 + 8) * PITCHH + c0) * 2), "r"(v1) : "memory");
                }
            }

            // Issue next-tile x prefetch EARLY (block 0, before GEMMs)
            if (b == 0) {
                int nxt = tile + NSM;
                if (nxt < ntiles && (long long)(nxt + 1) * 128 <= (long long)n) {
                    if (tid128 < 48) {
                        uint32_t dst = xbase + (uint32_t)((buf ^ 1) * 1536 + m0 * 12
                                                          + tid128 * 16);
                        const char* src = (const char*)x + (long long)nxt * 1536
                                          + m0 * 12 + tid128 * 16;
                        CP_ASYNC16(dst, src);
                    }
                    CP_COMMIT;
                    pf_next = true;
                } else {
                    pf_next = false;
                }
            }

            // Early GEMM: own k-chunks (A from registers, B resident) —
            // entirely pre-barrier.
            float acc[4][4][4];
            #pragma unroll
            for (int mt = 0; mt < 4; mt++)
                #pragma unroll
                for (int nt = 0; nt < 4; nt++) {
                    acc[mt][nt][0] = 0.f; acc[mt][nt][1] = 0.f;
                    acc[mt][nt][2] = 0.f; acc[mt][nt][3] = 0.f;
                }
            const uint32_t a_base = gbase + a_off;
            const uint32_t b_base = wbase + (uint32_t)b * TILE_HB + b_off;
            #pragma unroll
            for (int hk = 0; hk < 2; hk++) {
                const uint32_t koff = (uint32_t)(wn2 + hk) * 32;
                uint32_t bf[4][2];
                #pragma unroll
                for (int np = 0; np < 2; np++)
                    LDMATRIX_X4(bf[np*2][0], bf[np*2][1], bf[np*2+1][0], bf[np*2+1][1],
                                b_base + (uint32_t)np * (16 * PITCHH * 2) + koff);
                #pragma unroll
                for (int nt = 0; nt < 4; nt++)
                    #pragma unroll
                    for (int mt = 0; mt < 4; mt++)
                        MMA_BF16(acc[mt][nt],
                                 gq[hk][mt][0], gq[hk][mt][1],
                                 gq[hk][mt][2], gq[hk][mt][3],
                                 bf[nt][0], bf[nt][1]);
            }
            BAR_HALF(barid);   // single barrier: rsum + g rows visible

            // Late GEMM: remaining 6 k-chunks (A via ldmatrix)
            #pragma unroll
            for (int j = 0; j < 6; j++) {
                const int ks = j + ((j >= wn2) ? 2 : 0);
                const uint32_t koff = (uint32_t)ks * 32;
                uint32_t a[4][4];
                #pragma unroll
                for (int mt = 0; mt < 4; mt++)
                    LDMATRIX_X4(a[mt][0], a[mt][1], a[mt][2], a[mt][3],
                                a_base + (uint32_t)mt * (16 * PITCHH * 2) + koff);
                uint32_t bf[4][2];
                #pragma unroll
                for (int np = 0; np < 2; np++)
                    LDMATRIX_X4(bf[np*2][0], bf[np*2][1], bf[np*2+1][0], bf[np*2+1][1],
                                b_base + (uint32_t)np * (16 * PITCHH * 2) + koff);
                #pragma unroll
                for (int nt = 0; nt < 4; nt++)
                    #pragma unroll
                    for (int mt = 0; mt < 4; mt++)
                        MMA_BF16(acc[mt][nt],
                                 a[mt][0], a[mt][1], a[mt][2], a[mt][3],
                                 bf[nt][0], bf[nt][1]);
            }

            // Epilogue: sc from rsum (ordered by the barrier),
            // h += relu(acc*sc + bias)
            float2 bias2[4];
            #pragma unroll
            for (int nt = 0; nt < 4; nt++)
                bias2[nt] = *(const float2*)&bbs_s[b * HID + n0w + nt * 8 + 2 * tig];
            #pragma unroll
            for (int mt = 0; mt < 4; mt++) {
                int r0 = m0 + mt * 16 + gid;
                float4 s0 = *(const float4*)&rsb[r0 * 4];
                float4 s1 = *(const float4*)&rsb[(r0 + 8) * 4];
                float sc0 = rsqrtf((s0.x + s0.y + s0.z + s0.w) * (1.0f / HID) + RMS_EPS);
                float sc1 = rsqrtf((s1.x + s1.y + s1.z + s1.w) * (1.0f / HID) + RMS_EPS);
                #pragma unroll
                for (int nt = 0; nt < 4; nt++) {
                    int ix = (mt * 4 + nt) * 4;
                    hv[ix]     += fmaxf(fmaf(acc[mt][nt][0], sc0, bias2[nt].x), 0.0f);
                    hv[ix + 1] += fmaxf(fmaf(acc[mt][nt][1], sc0, bias2[nt].y), 0.0f);
                    hv[ix + 2] += fmaxf(fmaf(acc[mt][nt][2], sc1, bias2[nt].x), 0.0f);
                    hv[ix + 3] += fmaxf(fmaf(acc[mt][nt][3], sc1, bias2[nt].y), 0.0f);
                }
            }
        }

        // ---- Output projection (per-half reduction, rsum buf 0 — safe:
        // last buf-0 reads were epi of block 2, ordered by BAR of block 3)
        #pragma unroll
        for (int mt = 0; mt < 4; mt++) {
            float o0 = 0.f, o1 = 0.f;
            #pragma unroll
            for (int nt = 0; nt < 4; nt++) {
                int c0 = n0w + nt * 8 + 2 * tig;
                float2 w = *(const float2*)&wout_s[c0];
                o0 = fmaf(hv[(mt*4+nt)*4+0], w.x, fmaf(hv[(mt*4+nt)*4+1], w.y, o0));
                o1 = fmaf(hv[(mt*4+nt)*4+2], w.x, fmaf(hv[(mt*4+nt)*4+3], w.y, o1));
            }
            o0 += __shfl_xor_sync(0xffffffffu, o0, 1);
            o0 += __shfl_xor_sync(0xffffffffu, o0, 2);
            o1 += __shfl_xor_sync(0xffffffffu, o1, 1);
            o1 += __shfl_xor_sync(0xffffffffu, o1, 2);
            if (tig == 0) {
                int r0 = m0 + mt * 16 + gid;
                rsum[r0 * 4 + warp_n]       = o0;
                rsum[(r0 + 8) * 4 + warp_n] = o1;
            }
        }
        BAR_HALF(barid);
        if (tid128 < 64) {
            int r = m0 + tid128;
            long long gr = (long long)row0 + r;
            if (gr < n) {
                float4 s = *(const float4*)&rsum[r * 4];
                float lg = s.x + s.y + s.z + s.w + bout;
                float e = __expf(lg);
                out[gr] = e;
                atomicAdd(&g_ssum[ids[gr]], e);
            }
        }
    }
}

// ---------------------------------------------------------------------------
// Normalize: out[i] /= ssum[ids[i]], 8 elements per thread, fast divide
// ---------------------------------------------------------------------------
__global__ void seg_norm_kernel(const int* __restrict__ ids,
                                float* __restrict__ out, int n)
{
    int base = (blockIdx.x * blockDim.x + threadIdx.x) * 8;
    if (base + 7 < n) {
        #pragma unroll
        for (int q = 0; q < 2; q++) {
            int i = base + q * 4;
            int4   s = *(const int4*)&ids[i];
            float4 v = *(float4*)&out[i];
            v.x = __fdividef(v.x, g_ssum[s.x]);
            v.y = __fdividef(v.y, g_ssum[s.y]);
            v.z = __fdividef(v.z, g_ssum[s.z]);
            v.w = __fdividef(v.w, g_ssum[s.w]);
            *(float4*)&out[i] = v;
        }
    } else {
        for (int j = base; j < n; j++) out[j] = __fdividef(out[j], g_ssum[ids[j]]);
    }
}

// ---------------------------------------------------------------------------
extern "C" void kernel_launch(void* const* d_in, const int* in_sizes, int n_in,
                              void* d_out, int out_size)
{
    const float* x     = (const float*)d_in[0];
    const int*   ids   = (const int*)  d_in[1];
    const float* W_in  = (const float*)d_in[2];
    const float* b_in  = (const float*)d_in[3];
    const float* rms_w = (const float*)d_in[4];
    const float* W_res = (const float*)d_in[5];
    const float* b_res = (const float*)d_in[6];
    const float* W_out = (const float*)d_in[7];
    const float* b_out = (const float*)d_in[8];
    float* out = (float*)d_out;
    const int n = in_sizes[1];
    const int ntiles = (n + 127) / 128;

    cudaFuncSetAttribute(mlp_mma_kernel,
                         cudaFuncAttributeMaxDynamicSharedMemorySize,
                         SMEM_TOTAL);

    prep_kernel<<<(NSEG / 4 + 255) / 256, 256>>>(W_res);
    mlp_mma_kernel<<<NSM, THREADS, SMEM_TOTAL>>>(
        x, ids, W_in, b_in, rms_w, b_res, W_out, b_out, out, n, ntiles);
    seg_norm_kernel<<<((n + 7) / 8 + 255) / 256, 256>>>(ids, out, n);
}

// round 13
// speedup vs baseline: 2.7601x; 1.0180x over previous
#include <cuda_runtime.h>
#include <cuda_bf16.h>
#include <cstdint>
#include <math.h>

// Problem constants
#define NSEG 500000
#define HID 128
#define NBLK 4
#define THREADS 256
#define NSM 152              // persistent grid size (GB300 has 152 SMs)
#define PITCHH 136           // halfs per bf16 tile row (ldmatrix-conflict-free pad)
#define RMS_EPS 1.1920929e-07f

#define TILE_HB (128 * PITCHH * 2)          // bytes per 128x128 bf16 tile (34816)
#define OFF_W   0                            // 4 weight tiles
#define OFF_G   (4 * TILE_HB)                // 1 g tile (half-private rows)
#define OFF_RS  (5 * TILE_HB)                // rsum[3][128][4] floats (6144 B)
#define OFF_CST (OFF_RS + 6144)              // consts: 1664 floats (6656 B)
#define OFF_XS  (OFF_CST + 6656)             // xs double buffer 2*384 floats (3072 B)
#define SMEM_TOTAL (OFF_XS + 3072)

// Scratch (device globals — no allocation allowed)
__device__ float         g_ssum[NSEG];
__device__ __nv_bfloat16 g_wbf[NBLK * HID * HID];

__device__ __forceinline__ uint32_t smem_u32(const void* p) {
    uint32_t a;
    asm("{ .reg .u64 t; cvta.to.shared.u64 t, %1; cvt.u32.u64 %0, t; }"
        : "=r"(a) : "l"(p));
    return a;
}
__device__ __forceinline__ uint32_t bf16x2(float lo, float hi) {
    uint32_t r;
    asm("cvt.rn.bf16x2.f32 %0, %1, %2;" : "=r"(r) : "f"(hi), "f"(lo));
    return r;
}

#define CP_ASYNC16(dst, src) \
    asm volatile("cp.async.cg.shared.global [%0], [%1], 16;" \
                 :: "r"(dst), "l"(src) : "memory")
#define CP_COMMIT asm volatile("cp.async.commit_group;" ::: "memory")
#define CP_WAIT0  asm volatile("cp.async.wait_group 0;" ::: "memory")

// Half-CTA named barrier (128 threads each; ids 1 and 2)
#define BAR_HALF(id) asm volatile("bar.sync %0, 128;" :: "r"(id) : "memory")

#define LDMATRIX_X4(r0, r1, r2, r3, addr) \
    asm volatile("ldmatrix.sync.aligned.m8n8.x4.shared.b16 {%0,%1,%2,%3}, [%4];" \
                 : "=r"(r0), "=r"(r1), "=r"(r2), "=r"(r3) : "r"(addr))

#define MMA_BF16(d, a0, a1, a2, a3, b0, b1) \
    asm volatile("mma.sync.aligned.m16n8k16.row.col.f32.bf16.bf16.f32 " \
        "{%0,%1,%2,%3}, {%4,%5,%6,%7}, {%8,%9}, {%0,%1,%2,%3};" \
        : "+f"((d)[0]), "+f"((d)[1]), "+f"((d)[2]), "+f"((d)[3]) \
        : "r"(a0), "r"(a1), "r"(a2), "r"(a3), "r"(b0), "r"(b1))

// ---------------------------------------------------------------------------
// Prep: convert W to bf16 only (g_ssum zeroed by a memset node).
// ---------------------------------------------------------------------------
__global__ void prep_kernel(const float* __restrict__ W_res) {
    int i = blockIdx.x * blockDim.x + threadIdx.x;
    if (i < (NBLK * HID * HID) / 4) {
        float4 v = ((const float4*)W_res)[i];
        uint2 o;
        o.x = bf16x2(v.x, v.y);
        o.y = bf16x2(v.z, v.w);
        ((uint2*)g_wbf)[i] = o;
    }
}

// ---------------------------------------------------------------------------
// Persistent fused MLP (bf16 mma). h in fragment registers end-to-end.
// rmsnorm scale applied POST-GEMM. One barrier per res block; the x-tile
// visibility barrier is merged into the previous tile's out-proj barrier
// (CP_WAIT0 hoisted before it). rsum triple-buffered (blocks: 0/1, outproj: 2).
// ---------------------------------------------------------------------------
__global__ void __launch_bounds__(THREADS, 1)
mlp_mma_kernel(const float* __restrict__ x,
               const int*   __restrict__ ids,
               const float* __restrict__ W_in,
               const float* __restrict__ b_in,
               const float* __restrict__ rms_w,
               const float* __restrict__ b_res,
               const float* __restrict__ W_out,
               const float* __restrict__ b_out,
               float* __restrict__ out,
               int n, int ntiles)
{
    extern __shared__ char smem[];
    float* rsum   = (float*)(smem + OFF_RS);      // [3][128][4]
    float* win_s  = (float*)(smem + OFF_CST);     // 384
    float* bin_s  = win_s + 384;                  // 128
    float* rws_s  = bin_s + 128;                  // 512
    float* bbs_s  = rws_s + 512;                  // 512
    float* wout_s = bbs_s + 512;                  // 128
    float* xs_all = (float*)(smem + OFF_XS);      // [2][384]

    const int t      = threadIdx.x;
    const int warp   = t >> 5;
    const int lane   = t & 31;
    const int gid    = lane >> 2;
    const int tig    = lane & 3;
    const int warp_m = warp >> 2;       // 0..1 -> half id
    const int warp_n = warp & 3;
    const int m0     = warp_m * 64;
    const int n0w    = warp_n * 32;
    const int tid128 = t & 127;
    const int barid  = 1 + warp_m;
    const int wn2    = warp_n * 2;      // own k-chunk base

    const uint32_t wbase = smem_u32(smem + OFF_W);
    const uint32_t gbase = smem_u32(smem + OFF_G);
    const uint32_t xbase = smem_u32(xs_all);

    // ---- Stage consts once
    for (int i = t; i < 384; i += THREADS) win_s[i] = W_in[i];
    for (int i = t; i < 128; i += THREADS) {
        bin_s[i]  = b_in[i];
        wout_s[i] = W_out[i];
    }
    for (int i = t; i < 512; i += THREADS) {
        rws_s[i] = rms_w[i];
        bbs_s[i] = b_res[i];
    }
    // ---- Stage ALL 4 weight tiles once (bf16, 16B chunks)
    #pragma unroll
    for (int it = 0; it < 32; it++) {
        int i   = t + it * THREADS;     // 0..8191
        int nrg = i >> 4;               // blk*128 + row
        int kc  = i & 15;
        CP_ASYNC16(wbase + (uint32_t)(nrg * PITCHH + kc * 8) * 2,
                   g_wbf + nrg * HID + kc * 8);
    }
    CP_COMMIT;
    CP_WAIT0;
    __syncthreads();   // consts + W visible CTA-wide

    const float bout = b_out[0];

    // ldmatrix lane addresses (fixed)
    const uint32_t a_off = ((uint32_t)(m0 + (lane & 15)) * PITCHH
                           + (uint32_t)(lane >> 4) * 8) * 2;
    const int b_row = n0w + ((lane >> 4) * 8) + (lane & 7);
    const uint32_t b_off = ((uint32_t)b_row * PITCHH
                            + (uint32_t)(((lane >> 3) & 1) * 8)) * 2;

    bool pf_next = false;
    int  buf     = 0;

    for (int tile = blockIdx.x; tile < ntiles; tile += NSM, buf ^= 1) {
        const int row0 = tile * 128;
        float* xsb = xs_all + buf * 384;

        // Steady state: xs already prefetched AND made visible by the
        // previous tile's out-proj barrier (CP_WAIT0 hoisted before it).
        if (!pf_next) {
            for (int i = tid128; i < 192; i += 128) {
                int idx = m0 * 3 + i;
                long long gi = (long long)row0 * 3 + idx;
                xsb[idx] = (gi < 3LL * n) ? x[gi] : 0.0f;
            }
            BAR_HALF(barid);
        }

        // ---- In-projection into fragment registers
        float hv[64];
        {
            float wc[8][3], bc[8];
            #pragma unroll
            for (int nt = 0; nt < 4; nt++) {
                int c0 = n0w + nt * 8 + 2 * tig;
                #pragma unroll
                for (int k = 0; k < 3; k++) {
                    wc[nt * 2 + 0][k] = win_s[c0 * 3 + k];
                    wc[nt * 2 + 1][k] = win_s[(c0 + 1) * 3 + k];
                }
                bc[nt * 2 + 0] = bin_s[c0];
                bc[nt * 2 + 1] = bin_s[c0 + 1];
            }
            #pragma unroll
            for (int mt = 0; mt < 4; mt++) {
                int r0 = m0 + mt * 16 + gid;
                float a0 = xsb[r0 * 3], a1 = xsb[r0 * 3 + 1], a2 = xsb[r0 * 3 + 2];
                float d0 = xsb[(r0 + 8) * 3], d1 = xsb[(r0 + 8) * 3 + 1], d2 = xsb[(r0 + 8) * 3 + 2];
                #pragma unroll
                for (int nt = 0; nt < 4; nt++) {
                    #pragma unroll
                    for (int p = 0; p < 2; p++) {
                        float* w = wc[nt * 2 + p];
                        hv[(mt * 4 + nt) * 4 + p] =
                            fmaf(a2, w[2], fmaf(a1, w[1], fmaf(a0, w[0], bc[nt * 2 + p])));
                        hv[(mt * 4 + nt) * 4 + 2 + p] =
                            fmaf(d2, w[2], fmaf(d1, w[1], fmaf(d0, w[0], bc[nt * 2 + p])));
                    }
                }
            }
        }

        // ---- Residual blocks (ONE barrier each)
        for (int b = 0; b < NBLK; b++) {
            float* rsb = rsum + (b & 1) * 512;   // double-buffered rowsum

            // rms partial sumsq -> rsb
            #pragma unroll
            for (int mt = 0; mt < 4; mt++) {
                float p0 = 0.f, p1 = 0.f;
                #pragma unroll
                for (int nt = 0; nt < 4; nt++) {
                    float e0 = hv[(mt*4+nt)*4+0], e1 = hv[(mt*4+nt)*4+1];
                    float e2 = hv[(mt*4+nt)*4+2], e3 = hv[(mt*4+nt)*4+3];
                    p0 = fmaf(e0, e0, fmaf(e1, e1, p0));
                    p1 = fmaf(e2, e2, fmaf(e3, e3, p1));
                }
                p0 += __shfl_xor_sync(0xffffffffu, p0, 1);
                p0 += __shfl_xor_sync(0xffffffffu, p0, 2);
                p1 += __shfl_xor_sync(0xffffffffu, p1, 1);
                p1 += __shfl_xor_sync(0xffffffffu, p1, 2);
                if (tig == 0) {
                    int r0 = m0 + mt * 16 + gid;
                    rsb[r0 * 4 + warp_n]       = p0;
                    rsb[(r0 + 8) * 4 + warp_n] = p1;
                }
            }

            // quantize g = bf16(h * rms_w) — row scale applied post-GEMM
            uint32_t gq[2][4][4];   // [own-k half][mt][a-reg]
            #pragma unroll
            for (int mt = 0; mt < 4; mt++) {
                int r0 = m0 + mt * 16 + gid;
                #pragma unroll
                for (int nt = 0; nt < 4; nt++) {
                    int c0 = n0w + nt * 8 + 2 * tig;
                    float2 rw = *(const float2*)&rws_s[b * HID + c0];
                    uint32_t v0 = bf16x2(hv[(mt*4+nt)*4+0] * rw.x,
                                         hv[(mt*4+nt)*4+1] * rw.y);
                    uint32_t v1 = bf16x2(hv[(mt*4+nt)*4+2] * rw.x,
                                         hv[(mt*4+nt)*4+3] * rw.y);
                    gq[nt >> 1][mt][(nt & 1) * 2 + 0] = v0;
                    gq[nt >> 1][mt][(nt & 1) * 2 + 1] = v1;
                    asm volatile("st.shared.b32 [%0], %1;"
                        :: "r"(gbase + (uint32_t)(r0 * PITCHH + c0) * 2), "r"(v0) : "memory");
                    asm volatile("st.shared.b32 [%0], %1;"
                        :: "r"(gbase + (uint32_t)((r0 + 8) * PITCHH + c0) * 2), "r"(v1) : "memory");
                }
            }

            // Issue next-tile x prefetch EARLY (block 0, before GEMMs)
            if (b == 0) {
                int nxt = tile + NSM;
                if (nxt < ntiles && (long long)(nxt + 1) * 128 <= (long long)n) {
                    if (tid128 < 48) {
                        uint32_t dst = xbase + (uint32_t)((buf ^ 1) * 1536 + m0 * 12
                                                          + tid128 * 16);
                        const char* src = (const char*)x + (long long)nxt * 1536
                                          + m0 * 12 + tid128 * 16;
                        CP_ASYNC16(dst, src);
                    }
                    CP_COMMIT;
                    pf_next = true;
                } else {
                    pf_next = false;
                }
            }

            // Early GEMM: own k-chunks (A from registers, B resident)
            float acc[4][4][4];
            #pragma unroll
            for (int mt = 0; mt < 4; mt++)
                #pragma unroll
                for (int nt = 0; nt < 4; nt++) {
                    acc[mt][nt][0] = 0.f; acc[mt][nt][1] = 0.f;
                    acc[mt][nt][2] = 0.f; acc[mt][nt][3] = 0.f;
                }
            const uint32_t a_base = gbase + a_off;
            const uint32_t b_base = wbase + (uint32_t)b * TILE_HB + b_off;
            #pragma unroll
            for (int hk = 0; hk < 2; hk++) {
                const uint32_t koff = (uint32_t)(wn2 + hk) * 32;
                uint32_t bf[4][2];
                #pragma unroll
                for (int np = 0; np < 2; np++)
                    LDMATRIX_X4(bf[np*2][0], bf[np*2][1], bf[np*2+1][0], bf[np*2+1][1],
                                b_base + (uint32_t)np * (16 * PITCHH * 2) + koff);
                #pragma unroll
                for (int nt = 0; nt < 4; nt++)
                    #pragma unroll
                    for (int mt = 0; mt < 4; mt++)
                        MMA_BF16(acc[mt][nt],
                                 gq[hk][mt][0], gq[hk][mt][1],
                                 gq[hk][mt][2], gq[hk][mt][3],
                                 bf[nt][0], bf[nt][1]);
            }
            BAR_HALF(barid);   // single barrier: rsum + g rows visible

            // Late GEMM: remaining 6 k-chunks (A via ldmatrix)
            #pragma unroll
            for (int j = 0; j < 6; j++) {
                const int ks = j + ((j >= wn2) ? 2 : 0);
                const uint32_t koff = (uint32_t)ks * 32;
                uint32_t a[4][4];
                #pragma unroll
                for (int mt = 0; mt < 4; mt++)
                    LDMATRIX_X4(a[mt][0], a[mt][1], a[mt][2], a[mt][3],
                                a_base + (uint32_t)mt * (16 * PITCHH * 2) + koff);
                uint32_t bf[4][2];
                #pragma unroll
                for (int np = 0; np < 2; np++)
                    LDMATRIX_X4(bf[np*2][0], bf[np*2][1], bf[np*2+1][0], bf[np*2+1][1],
                                b_base + (uint32_t)np * (16 * PITCHH * 2) + koff);
                #pragma unroll
                for (int nt = 0; nt < 4; nt++)
                    #pragma unroll
                    for (int mt = 0; mt < 4; mt++)
                        MMA_BF16(acc[mt][nt],
                                 a[mt][0], a[mt][1], a[mt][2], a[mt][3],
                                 bf[nt][0], bf[nt][1]);
            }

            // Epilogue: sc from rsum (ordered by the barrier)
            float2 bias2[4];
            #pragma unroll
            for (int nt = 0; nt < 4; nt++)
                bias2[nt] = *(const float2*)&bbs_s[b * HID + n0w + nt * 8 + 2 * tig];
            #pragma unroll
            for (int mt = 0; mt < 4; mt++) {
                int r0 = m0 + mt * 16 + gid;
                float4 s0 = *(const float4*)&rsb[r0 * 4];
                float4 s1 = *(const float4*)&rsb[(r0 + 8) * 4];
                float sc0 = rsqrtf((s0.x + s0.y + s0.z + s0.w) * (1.0f / HID) + RMS_EPS);
                float sc1 = rsqrtf((s1.x + s1.y + s1.z + s1.w) * (1.0f / HID) + RMS_EPS);
                #pragma unroll
                for (int nt = 0; nt < 4; nt++) {
                    int ix = (mt * 4 + nt) * 4;
                    hv[ix]     += fmaxf(fmaf(acc[mt][nt][0], sc0, bias2[nt].x), 0.0f);
                    hv[ix + 1] += fmaxf(fmaf(acc[mt][nt][1], sc0, bias2[nt].y), 0.0f);
                    hv[ix + 2] += fmaxf(fmaf(acc[mt][nt][2], sc1, bias2[nt].x), 0.0f);
                    hv[ix + 3] += fmaxf(fmaf(acc[mt][nt][3], sc1, bias2[nt].y), 0.0f);
                }
            }
        }

        // ---- Output projection — dedicated rsum buffer 2 (no conflict with
        // the next tile's block-0 writes to buffer 0)
        float* rso = rsum + 1024;
        #pragma unroll
        for (int mt = 0; mt < 4; mt++) {
            float o0 = 0.f, o1 = 0.f;
            #pragma unroll
            for (int nt = 0; nt < 4; nt++) {
                int c0 = n0w + nt * 8 + 2 * tig;
                float2 w = *(const float2*)&wout_s[c0];
                o0 = fmaf(hv[(mt*4+nt)*4+0], w.x, fmaf(hv[(mt*4+nt)*4+1], w.y, o0));
                o1 = fmaf(hv[(mt*4+nt)*4+2], w.x, fmaf(hv[(mt*4+nt)*4+3], w.y, o1));
            }
            o0 += __shfl_xor_sync(0xffffffffu, o0, 1);
            o0 += __shfl_xor_sync(0xffffffffu, o0, 2);
            o1 += __shfl_xor_sync(0xffffffffu, o1, 1);
            o1 += __shfl_xor_sync(0xffffffffu, o1, 2);
            if (tig == 0) {
                int r0 = m0 + mt * 16 + gid;
                rso[r0 * 4 + warp_n]       = o0;
                rso[(r0 + 8) * 4 + warp_n] = o1;
            }
        }
        CP_WAIT0;          // next tile's xs landed (issued in block 0)
        BAR_HALF(barid);   // orders rso AND xs for everyone in the half
        if (tid128 < 64) {
            int r = m0 + tid128;
            long long gr = (long long)row0 + r;
            if (gr < n) {
                float4 s = *(const float4*)&rso[r * 4];
                float lg = s.x + s.y + s.z + s.w + bout;
                float e = __expf(lg);
                out[gr] = e;
                atomicAdd(&g_ssum[ids[gr]], e);
            }
        }
        // rso reads precede the next tile's first block BAR in program order;
        // next out-proj write to rso is a full tile away -> safe.
    }
}

// ---------------------------------------------------------------------------
// Normalize: out[i] /= ssum[ids[i]], 8 elements per thread, fast divide
// ---------------------------------------------------------------------------
__global__ void seg_norm_kernel(const int* __restrict__ ids,
                                float* __restrict__ out, int n)
{
    int base = (blockIdx.x * blockDim.x + threadIdx.x) * 8;
    if (base + 7 < n) {
        #pragma unroll
        for (int q = 0; q < 2; q++) {
            int i = base + q * 4;
            int4   s = *(const int4*)&ids[i];
            float4 v = *(float4*)&out[i];
            v.x = __fdividef(v.x, g_ssum[s.x]);
            v.y = __fdividef(v.y, g_ssum[s.y]);
            v.z = __fdividef(v.z, g_ssum[s.z]);
            v.w = __fdividef(v.w, g_ssum[s.w]);
            *(float4*)&out[i] = v;
        }
    } else {
        for (int j = base; j < n; j++) out[j] = __fdividef(out[j], g_ssum[ids[j]]);
    }
}

// ---------------------------------------------------------------------------
extern "C" void kernel_launch(void* const* d_in, const int* in_sizes, int n_in,
                              void* d_out, int out_size)
{
    const float* x     = (const float*)d_in[0];
    const int*   ids   = (const int*)  d_in[1];
    const float* W_in  = (const float*)d_in[2];
    const float* b_in  = (const float*)d_in[3];
    const float* rms_w = (const float*)d_in[4];
    const float* W_res = (const float*)d_in[5];
    const float* b_res = (const float*)d_in[6];
    const float* W_out = (const float*)d_in[7];
    const float* b_out = (const float*)d_in[8];
    float* out = (float*)d_out;
    const int n = in_sizes[1];
    const int ntiles = (n + 127) / 128;

    static void* ssum_ptr = nullptr;
    if (!ssum_ptr) {
        cudaGetSymbolAddress(&ssum_ptr, g_ssum);
        cudaFuncSetAttribute(mlp_mma_kernel,
                             cudaFuncAttributeMaxDynamicSharedMemorySize,
                             SMEM_TOTAL);
    }

    cudaMemsetAsync(ssum_ptr, 0, NSEG * sizeof(float));   // graph memset node
    prep_kernel<<<(NBLK * HID * HID / 4 + 255) / 256, 256>>>(W_res);
    mlp_mma_kernel<<<NSM, THREADS, SMEM_TOTAL>>>(
        x, ids, W_in, b_in, rms_w, b_res, W_out, b_out, out, n, ntiles);
    seg_norm_kernel<<<((n + 7) / 8 + 255) / 256, 256>>>(ids, out, n);
}